// round 6
// baseline (speedup 1.0000x reference)
#include <cuda_runtime.h>
#include <cuda_fp16.h>
#include <math.h>
#include <stdint.h>

#define NN 100000
#define NE 1600000

// ---------------- scratch (device globals) ----------------
__device__ __half g_yh[(size_t)NN * 128];  // dinv-scaled XW, fp16
__device__ __half g_h[(size_t)NN * 128];   // layer activations fp16
__device__ float  g_dinv[NN];
__device__ int    g_cnt[NN];
__device__ int    g_excl[NN];
__device__ int    g_bsum[128];
__device__ int    g_rowptr[NN + 1];
__device__ int    g_cursor[NN];
__device__ int    g_col[NE];

// ---------------- prep ----------------
__global__ void zero_cnt(int* cnt, int n) {
    int i = blockIdx.x * blockDim.x + threadIdx.x;
    if (i < n) cnt[i] = 0;
}

__global__ void count_deg(const int* __restrict__ dst, int* __restrict__ cnt, int E, int N) {
    int e = blockIdx.x * blockDim.x + threadIdx.x;
    if (e >= E) return;
    int d = dst[e];
    if ((unsigned)d < (unsigned)N) atomicAdd(&cnt[d], 1);
}

// block scan + dinv fused (dinv[i] = rsqrt(cnt[i]+1))
__global__ void scan_block_dinv(const int* __restrict__ cnt, int* __restrict__ excl,
                                int* __restrict__ bsum, float* __restrict__ dinv, int n) {
    __shared__ int sh[1024];
    int tid = threadIdx.x;
    int i = blockIdx.x * 1024 + tid;
    int v = (i < n) ? cnt[i] : 0;
    if (i < n) dinv[i] = rsqrtf((float)(v + 1));
    sh[tid] = v;
    __syncthreads();
#pragma unroll
    for (int off = 1; off < 1024; off <<= 1) {
        int t = (tid >= off) ? sh[tid - off] : 0;
        __syncthreads();
        sh[tid] += t;
        __syncthreads();
    }
    if (i < n) excl[i] = sh[tid] - v;
    if (tid == 1023) bsum[blockIdx.x] = sh[1023];
}

__global__ void scan_partials(int* bsum, int nb) {
    __shared__ int sh[128];
    int tid = threadIdx.x;
    int v = (tid < nb) ? bsum[tid] : 0;
    sh[tid] = v;
    __syncthreads();
#pragma unroll
    for (int off = 1; off < 128; off <<= 1) {
        int t = (tid >= off) ? sh[tid - off] : 0;
        __syncthreads();
        sh[tid] += t;
        __syncthreads();
    }
    if (tid < nb) bsum[tid] = sh[tid] - v;
}

__global__ void scan_finish(const int* __restrict__ excl, const int* __restrict__ bsum,
                            int* __restrict__ rowptr, int* __restrict__ cursor, int n, int E) {
    int i = blockIdx.x * blockDim.x + threadIdx.x;
    if (i < n) {
        int v = excl[i] + bsum[i >> 10];
        rowptr[i] = v;
        cursor[i] = v;
    } else if (i == n) {
        rowptr[n] = E;
    }
}

__global__ void fill_csr(const int* __restrict__ src, const int* __restrict__ dst,
                         int* __restrict__ cursor, int* __restrict__ col, int E, int N) {
    int e = blockIdx.x * blockDim.x + threadIdx.x;
    if (e >= E) return;
    int d = dst[e];
    if ((unsigned)d >= (unsigned)N) return;
    int p = atomicAdd(&cursor[d], 1);
    col[p] = src[e];
}

// ---------------- HMMA GEMM: Yh = half(dinv * (X @ W)) ----------------
// IN32: input is fp32 (layer 1), converted during staging. Else fp16.
#define LDSM_X4(r0, r1, r2, r3, addr) \
    asm volatile("ldmatrix.sync.aligned.m8n8.x4.shared.b16 {%0,%1,%2,%3}, [%4];" \
                 : "=r"(r0), "=r"(r1), "=r"(r2), "=r"(r3) : "r"(addr))
#define LDSM_X4_T(r0, r1, r2, r3, addr) \
    asm volatile("ldmatrix.sync.aligned.m8n8.x4.trans.shared.b16 {%0,%1,%2,%3}, [%4];" \
                 : "=r"(r0), "=r"(r1), "=r"(r2), "=r"(r3) : "r"(addr))
#define MMA_16816(d, a, b) \
    asm volatile("mma.sync.aligned.m16n8k16.row.col.f32.f16.f16.f32 " \
                 "{%0,%1,%2,%3}, {%4,%5,%6,%7}, {%8,%9}, {%0,%1,%2,%3};" \
                 : "+f"(d[0]), "+f"(d[1]), "+f"(d[2]), "+f"(d[3]) \
                 : "r"(a[0]), "r"(a[1]), "r"(a[2]), "r"(a[3]), "r"(b[0]), "r"(b[1]))

template <int FO, bool IN32>
__launch_bounds__(256, 2)
__global__ void gemm_hmma(const void* __restrict__ Xin, const float* __restrict__ W,
                          const float* __restrict__ dinv, __half* __restrict__ Yh, int N) {
    constexpr int K = 128;
    constexpr int BM = 128;
    constexpr int WN = FO / 2;
    constexpr int NFRAG = WN / 8;
    constexpr int XROWB = K * 2;
    constexpr int WROWB = FO * 2;

    extern __shared__ char sm[];
    char* Xs = sm;
    char* Ws = sm + BM * XROWB;

    int tid = threadIdx.x;
    int warp = tid >> 5;
    int l = tid & 31;
    int warp_m = warp & 3;
    int warp_n = warp >> 2;
    int row0 = blockIdx.x * BM;

    // ---- stage X tile: 16B chunks, swizzled ----
    {
        constexpr int CHUNKS = BM * K * 2 / 16;  // 2048
        for (int i = tid; i < CHUNKS; i += 256) {
            int r = i >> 4;
            int q = i & 15;
            int gr = row0 + r;
            uint4 v = make_uint4(0, 0, 0, 0);
            if (gr < N) {
                if (IN32) {
                    const float4* p = (const float4*)Xin + (size_t)gr * 32 + q * 2;
                    float4 f0 = p[0];
                    float4 f1 = p[1];
                    __half2 h0 = __floats2half2_rn(f0.x, f0.y);
                    __half2 h1 = __floats2half2_rn(f0.z, f0.w);
                    __half2 h2 = __floats2half2_rn(f1.x, f1.y);
                    __half2 h3 = __floats2half2_rn(f1.z, f1.w);
                    v.x = *(unsigned*)&h0;
                    v.y = *(unsigned*)&h1;
                    v.z = *(unsigned*)&h2;
                    v.w = *(unsigned*)&h3;
                } else {
                    v = *((const uint4*)Xin + (size_t)gr * 16 + q);
                }
            }
            *(uint4*)&Xs[r * XROWB + ((q ^ (r & 7)) << 4)] = v;
        }
    }
    // ---- stage W (fp32 -> fp16), swizzled ----
    {
        for (int i = tid; i < K * FO / 4; i += 256) {
            int k = i / (FO / 4);
            int c4 = i % (FO / 4);
            float4 v = ((const float4*)W)[(size_t)k * (FO / 4) + c4];
            __half2 h0 = __floats2half2_rn(v.x, v.y);
            __half2 h1 = __floats2half2_rn(v.z, v.w);
            uint2 u;
            u.x = *(unsigned*)&h0;
            u.y = *(unsigned*)&h1;
            int chunk = c4 >> 1;
            *(uint2*)&Ws[k * WROWB + (((chunk ^ (k & 7)) << 4) | ((c4 & 1) << 3))] = u;
        }
    }
    __syncthreads();

    unsigned xs_base = (unsigned)__cvta_generic_to_shared(Xs);
    unsigned ws_base = (unsigned)__cvta_generic_to_shared(Ws);

    float acc[2][NFRAG][4];
#pragma unroll
    for (int mf = 0; mf < 2; mf++)
#pragma unroll
        for (int nf = 0; nf < NFRAG; nf++)
#pragma unroll
            for (int c = 0; c < 4; c++) acc[mf][nf][c] = 0.f;

#pragma unroll
    for (int ks = 0; ks < 8; ks++) {
        unsigned a[2][4];
#pragma unroll
        for (int mf = 0; mf < 2; mf++) {
            int row = warp_m * 32 + mf * 16 + (l & 15);
            int colh = ks * 16 + (l >> 4) * 8;
            unsigned addr = xs_base + row * XROWB + ((((colh >> 3) ^ (row & 7))) << 4);
            LDSM_X4(a[mf][0], a[mf][1], a[mf][2], a[mf][3], addr);
        }
        unsigned b[NFRAG][2];
#pragma unroll
        for (int g2 = 0; g2 < NFRAG / 2; g2++) {
            int brow = ks * 16 + (l & 15);
            int bcol = warp_n * WN + g2 * 16 + (l >> 4) * 8;
            unsigned addr = ws_base + brow * WROWB + ((((bcol >> 3) ^ (brow & 7))) << 4);
            unsigned r0, r1, r2, r3;
            LDSM_X4_T(r0, r1, r2, r3, addr);
            b[2 * g2][0] = r0; b[2 * g2][1] = r1;
            b[2 * g2 + 1][0] = r2; b[2 * g2 + 1][1] = r3;
        }
#pragma unroll
        for (int mf = 0; mf < 2; mf++)
#pragma unroll
            for (int nf = 0; nf < NFRAG; nf++)
                MMA_16816(acc[mf][nf], a[mf], b[nf]);
    }

    int g = l >> 2;
    int c2 = (l & 3) * 2;
#pragma unroll
    for (int mf = 0; mf < 2; mf++) {
        int r_lo = row0 + warp_m * 32 + mf * 16 + g;
        int r_hi = r_lo + 8;
        float di_lo = (r_lo < N) ? dinv[r_lo] : 0.f;
        float di_hi = (r_hi < N) ? dinv[r_hi] : 0.f;
#pragma unroll
        for (int nf = 0; nf < NFRAG; nf++) {
            int col = warp_n * WN + nf * 8 + c2;
            if (r_lo < N) {
                __half2 h = __floats2half2_rn(di_lo * acc[mf][nf][0], di_lo * acc[mf][nf][1]);
                *(__half2*)&Yh[(size_t)r_lo * FO + col] = h;
            }
            if (r_hi < N) {
                __half2 h = __floats2half2_rn(di_hi * acc[mf][nf][2], di_hi * acc[mf][nf][3]);
                *(__half2*)&Yh[(size_t)r_hi * FO + col] = h;
            }
        }
    }
}

// ---------------- aggregation helpers ----------------
__device__ __forceinline__ void unpack_add8(uint4 u, float* acc) {
    float2 f;
    f = __half22float2(*(__half2*)&u.x); acc[0] += f.x; acc[1] += f.y;
    f = __half22float2(*(__half2*)&u.y); acc[2] += f.x; acc[3] += f.y;
    f = __half22float2(*(__half2*)&u.z); acc[4] += f.x; acc[5] += f.y;
    f = __half22float2(*(__half2*)&u.w); acc[6] += f.x; acc[7] += f.y;
}

// ---------------- agg + relu: warp per node, 2 edges/warp, 128 ch, fp16 out ----------------
__global__ void agg_relu128(const int* __restrict__ rowptr, const int* __restrict__ col,
                            const __half* __restrict__ Yh, const float* __restrict__ dinv,
                            const float* __restrict__ bias, __half* __restrict__ H, int N) {
    int node = (blockIdx.x * blockDim.x + threadIdx.x) >> 5;
    int lane = threadIdx.x & 31;
    if (node >= N) return;
    int hf = lane >> 4;
    int l16 = lane & 15;
    const uint4* Y4 = (const uint4*)Yh;   // 16 uint4 per 128-ch row

    float acc[8];
#pragma unroll
    for (int k = 0; k < 8; k++) acc[k] = 0.f;
    if (hf == 0)
        unpack_add8(Y4[(size_t)node * 16 + l16], acc);   // self-loop

    int end = rowptr[node + 1];
    int j = rowptr[node] + hf;
    // 2 edges per half in flight (4 edges/warp-iter), stride 2 within half
    for (; j + 2 < end; j += 4) {
        int s0 = __ldg(&col[j]);
        int s1 = __ldg(&col[j + 2]);
        uint4 a = Y4[(size_t)s0 * 16 + l16];
        uint4 b = Y4[(size_t)s1 * 16 + l16];
        unpack_add8(a, acc);
        unpack_add8(b, acc);
    }
    for (; j < end; j += 2) {
        int s = __ldg(&col[j]);
        unpack_add8(Y4[(size_t)s * 16 + l16], acc);
    }
    // combine the two halves
#pragma unroll
    for (int k = 0; k < 8; k++)
        acc[k] += __shfl_xor_sync(0xFFFFFFFFu, acc[k], 16);

    if (hf == 0) {
        float di = dinv[node];
        float4 b0 = ((const float4*)bias)[l16 * 2];
        float4 b1 = ((const float4*)bias)[l16 * 2 + 1];
        __half2 p0 = __floats2half2_rn(fmaxf(fmaf(di, acc[0], b0.x), 0.f),
                                       fmaxf(fmaf(di, acc[1], b0.y), 0.f));
        __half2 p1 = __floats2half2_rn(fmaxf(fmaf(di, acc[2], b0.z), 0.f),
                                       fmaxf(fmaf(di, acc[3], b0.w), 0.f));
        __half2 p2 = __floats2half2_rn(fmaxf(fmaf(di, acc[4], b1.x), 0.f),
                                       fmaxf(fmaf(di, acc[5], b1.y), 0.f));
        __half2 p3 = __floats2half2_rn(fmaxf(fmaf(di, acc[6], b1.z), 0.f),
                                       fmaxf(fmaf(di, acc[7], b1.w), 0.f));
        uint4 u;
        u.x = *(unsigned*)&p0;
        u.y = *(unsigned*)&p1;
        u.z = *(unsigned*)&p2;
        u.w = *(unsigned*)&p3;
        ((uint4*)H)[(size_t)node * 16 + l16] = u;
    }
}

// ---------------- agg + log_softmax: warp per node, 64 ch ----------------
__global__ void agg_lsm64(const int* __restrict__ rowptr, const int* __restrict__ col,
                          const __half* __restrict__ Yh, const float* __restrict__ dinv,
                          const float* __restrict__ bias, float2* __restrict__ Out, int N) {
    int node = (blockIdx.x * blockDim.x + threadIdx.x) >> 5;
    int lane = threadIdx.x & 31;
    if (node >= N) return;
    const unsigned* Y1 = (const unsigned*)Yh;
    float2 acc;
    {
        unsigned u = Y1[(size_t)node * 32 + lane];
        acc = __half22float2(*(__half2*)&u);
    }
    int j = rowptr[node];
    int end = rowptr[node + 1];
    for (; j + 4 <= end; j += 4) {
        int s0 = __ldg(&col[j]);
        int s1 = __ldg(&col[j + 1]);
        int s2 = __ldg(&col[j + 2]);
        int s3 = __ldg(&col[j + 3]);
        unsigned u0 = Y1[(size_t)s0 * 32 + lane];
        unsigned u1 = Y1[(size_t)s1 * 32 + lane];
        unsigned u2 = Y1[(size_t)s2 * 32 + lane];
        unsigned u3 = Y1[(size_t)s3 * 32 + lane];
        float2 v0 = __half22float2(*(__half2*)&u0);
        float2 v1 = __half22float2(*(__half2*)&u1);
        float2 v2 = __half22float2(*(__half2*)&u2);
        float2 v3 = __half22float2(*(__half2*)&u3);
        acc.x += v0.x + v1.x + v2.x + v3.x;
        acc.y += v0.y + v1.y + v2.y + v3.y;
    }
    for (; j < end; j++) {
        int s = __ldg(&col[j]);
        unsigned u = Y1[(size_t)s * 32 + lane];
        float2 v = __half22float2(*(__half2*)&u);
        acc.x += v.x; acc.y += v.y;
    }
    float di = dinv[node];
    float2 b = ((const float2*)bias)[lane];
    float vx = fmaf(di, acc.x, b.x);
    float vy = fmaf(di, acc.y, b.y);
    float m = fmaxf(vx, vy);
#pragma unroll
    for (int o = 16; o > 0; o >>= 1)
        m = fmaxf(m, __shfl_xor_sync(0xFFFFFFFFu, m, o));
    float s = expf(vx - m) + expf(vy - m);
#pragma unroll
    for (int o = 16; o > 0; o >>= 1)
        s += __shfl_xor_sync(0xFFFFFFFFu, s, o);
    float ls = m + logf(s);
    float2 o2;
    o2.x = vx - ls;
    o2.y = vy - ls;
    Out[(size_t)node * 32 + lane] = o2;
}

// ---------------- driver ----------------
extern "C" void kernel_launch(void* const* d_in, const int* in_sizes, int n_in,
                              void* d_out, int out_size) {
    const float* x   = (const float*)d_in[0];
    const int*   ei  = (const int*)d_in[1];
    const float* W1  = (const float*)d_in[2];
    const float* b1  = (const float*)d_in[3];
    const float* W2  = (const float*)d_in[4];
    const float* b2  = (const float*)d_in[5];
    const float* W3  = (const float*)d_in[6];
    const float* b3  = (const float*)d_in[7];
    float* out = (float*)d_out;

    int N = in_sizes[0] / 128;
    int E = in_sizes[1] / 2;
    const int* src = ei;
    const int* dst = ei + E;

    __half *yh, *h;
    float* dinv;
    int *cnt, *excl, *bsum, *rowptr, *cursor, *col;
    cudaGetSymbolAddress((void**)&yh, g_yh);
    cudaGetSymbolAddress((void**)&h, g_h);
    cudaGetSymbolAddress((void**)&dinv, g_dinv);
    cudaGetSymbolAddress((void**)&cnt, g_cnt);
    cudaGetSymbolAddress((void**)&excl, g_excl);
    cudaGetSymbolAddress((void**)&bsum, g_bsum);
    cudaGetSymbolAddress((void**)&rowptr, g_rowptr);
    cudaGetSymbolAddress((void**)&cursor, g_cursor);
    cudaGetSymbolAddress((void**)&col, g_col);

    constexpr int SMEM128 = 128 * 256 + 128 * 256;  // 65536
    constexpr int SMEM64  = 128 * 256 + 128 * 128;  // 49152
    cudaFuncSetAttribute(gemm_hmma<128, true>,  cudaFuncAttributeMaxDynamicSharedMemorySize, SMEM128);
    cudaFuncSetAttribute(gemm_hmma<128, false>, cudaFuncAttributeMaxDynamicSharedMemorySize, SMEM128);
    cudaFuncSetAttribute(gemm_hmma<64, false>,  cudaFuncAttributeMaxDynamicSharedMemorySize, SMEM64);

    int nb_nodes = (N + 255) / 256;
    int nb_edges = (E + 255) / 256;
    int nb_scan  = (N + 1023) / 1024;
    int gemm_blocks = (N + 127) / 128;
    int agg_blocks  = ((size_t)N * 32 + 255) / 256;

    // launch order: gemm1 is the 4th launch (profiler capture slot)
    zero_cnt<<<nb_nodes, 256>>>(cnt, N);                                    // 1
    count_deg<<<nb_edges, 256>>>(dst, cnt, E, N);                           // 2
    scan_block_dinv<<<nb_scan, 1024>>>(cnt, excl, bsum, dinv, N);           // 3
    gemm_hmma<128, true><<<gemm_blocks, 256, SMEM128>>>(x, W1, dinv, yh, N); // 4 <- profiled
    scan_partials<<<1, 128>>>(bsum, nb_scan);                               // 5
    scan_finish<<<(N + 256) / 256, 256>>>(excl, bsum, rowptr, cursor, N, E); // 6
    fill_csr<<<nb_edges, 256>>>(src, dst, cursor, col, E, N);               // 7

    // ---- layer 1 aggregation ----
    agg_relu128<<<agg_blocks, 256>>>(rowptr, col, yh, dinv, b1, h, N);
    // ---- layer 2 ----
    gemm_hmma<128, false><<<gemm_blocks, 256, SMEM128>>>(h, W2, dinv, yh, N);
    agg_relu128<<<agg_blocks, 256>>>(rowptr, col, yh, dinv, b2, h, N);
    // ---- layer 3 ----
    gemm_hmma<64, false><<<gemm_blocks, 256, SMEM64>>>(h, W3, dinv, yh, N);
    agg_lsm64<<<agg_blocks, 256>>>(rowptr, col, yh, dinv, b3, (float2*)out, N);
}

// round 7
// speedup vs baseline: 1.1120x; 1.1120x over previous
#include <cuda_runtime.h>
#include <cuda_fp16.h>
#include <math.h>
#include <stdint.h>

#define NN 100000
#define NE 1600000

// ---------------- scratch (device globals) ----------------
__device__ __half g_yh[(size_t)NN * 128];
__device__ __half g_h[(size_t)NN * 128];
__device__ float  g_dinv[NN];
__device__ int    g_cnt[NN];
__device__ int    g_excl[NN];
__device__ int    g_bsum[128];
__device__ int    g_rowptr[NN + 1];
__device__ int    g_cursor[NN];
__device__ int    g_col[NE];

// ---------------- prep ----------------
__global__ void zero_cnt(int* cnt, int n) {
    int i = blockIdx.x * blockDim.x + threadIdx.x;
    if (i < n) cnt[i] = 0;
}

__global__ void count_deg(const int* __restrict__ dst, int* __restrict__ cnt, int E, int N) {
    int e = blockIdx.x * blockDim.x + threadIdx.x;
    if (e >= E) return;
    int d = dst[e];
    if ((unsigned)d < (unsigned)N) atomicAdd(&cnt[d], 1);
}

__global__ void scan_block_dinv(const int* __restrict__ cnt, int* __restrict__ excl,
                                int* __restrict__ bsum, float* __restrict__ dinv, int n) {
    __shared__ int sh[1024];
    int tid = threadIdx.x;
    int i = blockIdx.x * 1024 + tid;
    int v = (i < n) ? cnt[i] : 0;
    if (i < n) dinv[i] = rsqrtf((float)(v + 1));
    sh[tid] = v;
    __syncthreads();
#pragma unroll
    for (int off = 1; off < 1024; off <<= 1) {
        int t = (tid >= off) ? sh[tid - off] : 0;
        __syncthreads();
        sh[tid] += t;
        __syncthreads();
    }
    if (i < n) excl[i] = sh[tid] - v;
    if (tid == 1023) bsum[blockIdx.x] = sh[1023];
}

__global__ void scan_partials(int* bsum, int nb) {
    __shared__ int sh[128];
    int tid = threadIdx.x;
    int v = (tid < nb) ? bsum[tid] : 0;
    sh[tid] = v;
    __syncthreads();
#pragma unroll
    for (int off = 1; off < 128; off <<= 1) {
        int t = (tid >= off) ? sh[tid - off] : 0;
        __syncthreads();
        sh[tid] += t;
        __syncthreads();
    }
    if (tid < nb) bsum[tid] = sh[tid] - v;
}

__global__ void scan_finish(const int* __restrict__ excl, const int* __restrict__ bsum,
                            int* __restrict__ rowptr, int* __restrict__ cursor, int n, int E) {
    int i = blockIdx.x * blockDim.x + threadIdx.x;
    if (i < n) {
        int v = excl[i] + bsum[i >> 10];
        rowptr[i] = v;
        cursor[i] = v;
    } else if (i == n) {
        rowptr[n] = E;
    }
}

__global__ void fill_csr(const int* __restrict__ src, const int* __restrict__ dst,
                         int* __restrict__ cursor, int* __restrict__ col, int E, int N) {
    int e = blockIdx.x * blockDim.x + threadIdx.x;
    if (e >= E) return;
    int d = dst[e];
    if ((unsigned)d >= (unsigned)N) return;
    int p = atomicAdd(&cursor[d], 1);
    col[p] = src[e];
}

// ---------------- persistent pipelined HMMA GEMM ----------------
#define LDSM_X4(r0, r1, r2, r3, addr) \
    asm volatile("ldmatrix.sync.aligned.m8n8.x4.shared.b16 {%0,%1,%2,%3}, [%4];" \
                 : "=r"(r0), "=r"(r1), "=r"(r2), "=r"(r3) : "r"(addr))
#define LDSM_X4_T(r0, r1, r2, r3, addr) \
    asm volatile("ldmatrix.sync.aligned.m8n8.x4.trans.shared.b16 {%0,%1,%2,%3}, [%4];" \
                 : "=r"(r0), "=r"(r1), "=r"(r2), "=r"(r3) : "r"(addr))
#define MMA_16816(d, a, b) \
    asm volatile("mma.sync.aligned.m16n8k16.row.col.f32.f16.f16.f32 " \
                 "{%0,%1,%2,%3}, {%4,%5,%6,%7}, {%8,%9}, {%0,%1,%2,%3};" \
                 : "+f"(d[0]), "+f"(d[1]), "+f"(d[2]), "+f"(d[3]) \
                 : "r"(a[0]), "r"(a[1]), "r"(a[2]), "r"(a[3]), "r"(b[0]), "r"(b[1]))

template <int FO, bool IN32>
__launch_bounds__(256, 2)
__global__ void gemm_hmma(const void* __restrict__ Xin, const float* __restrict__ W,
                          const float* __restrict__ dinv, __half* __restrict__ Yh, int N) {
    constexpr int K = 128;
    constexpr int BM = 128;
    constexpr int WN = FO / 2;
    constexpr int NFRAG = WN / 8;
    constexpr int XROWB = K * 2;      // 256 B
    constexpr int WROWB = FO * 2;

    extern __shared__ char sm[];
    char* Xs = sm;                    // [BM][K] fp16 swizzled (32 KB)
    char* Ws = sm + BM * XROWB;       // [K][FO] fp16 swizzled

    int tid = threadIdx.x;
    int warp = tid >> 5;
    int l = tid & 31;
    int warp_m = warp & 3;
    int warp_n = warp >> 2;

    // ---- stage W once per CTA (fp32 -> fp16, swizzled) ----
    for (int i = tid; i < K * FO / 4; i += 256) {
        int k = i / (FO / 4);
        int c4 = i % (FO / 4);
        float4 v = ((const float4*)W)[(size_t)k * (FO / 4) + c4];
        __half2 h0 = __floats2half2_rn(v.x, v.y);
        __half2 h1 = __floats2half2_rn(v.z, v.w);
        uint2 u;
        u.x = *(unsigned*)&h0;
        u.y = *(unsigned*)&h1;
        int chunk = c4 >> 1;
        *(uint2*)&Ws[k * WROWB + (((chunk ^ (k & 7)) << 4) | ((c4 & 1) << 3))] = u;
    }

    unsigned xs_base = (unsigned)__cvta_generic_to_shared(Xs);
    unsigned ws_base = (unsigned)__cvta_generic_to_shared(Ws);

    int tiles = (N + BM - 1) / BM;
    int t = blockIdx.x;

    // ---- prefetch registers: 8 x uint4 = one 128x128 fp16 tile / 256 thr ----
    uint4 pf[8];

    auto ldg_tile = [&](int row0) {
#pragma unroll
        for (int j = 0; j < 8; j++) {
            int i = tid + j * 256;
            int r = i >> 4;
            int q = i & 15;
            int gr = row0 + r;
            uint4 v = make_uint4(0, 0, 0, 0);
            if (gr < N) {
                if (IN32) {
                    const float4* p = (const float4*)Xin + (size_t)gr * 32 + q * 2;
                    float4 f0 = p[0];
                    float4 f1 = p[1];
                    __half2 h0 = __floats2half2_rn(f0.x, f0.y);
                    __half2 h1 = __floats2half2_rn(f0.z, f0.w);
                    __half2 h2 = __floats2half2_rn(f1.x, f1.y);
                    __half2 h3 = __floats2half2_rn(f1.z, f1.w);
                    v.x = *(unsigned*)&h0;
                    v.y = *(unsigned*)&h1;
                    v.z = *(unsigned*)&h2;
                    v.w = *(unsigned*)&h3;
                } else {
                    v = *((const uint4*)Xin + (size_t)gr * 16 + q);
                }
            }
            pf[j] = v;
        }
    };

    if (t < tiles) ldg_tile(t * BM);

    for (; t < tiles; t += gridDim.x) {
        int row0 = t * BM;
        // commit prefetched tile to smem
#pragma unroll
        for (int j = 0; j < 8; j++) {
            int i = tid + j * 256;
            int r = i >> 4;
            int q = i & 15;
            *(uint4*)&Xs[r * XROWB + ((q ^ (r & 7)) << 4)] = pf[j];
        }
        __syncthreads();   // X tile (and W, first iter) visible

        // issue loads for next tile while computing this one
        int tn = t + gridDim.x;
        if (tn < tiles) ldg_tile(tn * BM);

        float acc[2][NFRAG][4];
#pragma unroll
        for (int mf = 0; mf < 2; mf++)
#pragma unroll
            for (int nf = 0; nf < NFRAG; nf++)
#pragma unroll
                for (int c = 0; c < 4; c++) acc[mf][nf][c] = 0.f;

#pragma unroll
        for (int ks = 0; ks < 8; ks++) {
            unsigned a[2][4];
#pragma unroll
            for (int mf = 0; mf < 2; mf++) {
                int row = warp_m * 32 + mf * 16 + (l & 15);
                int colh = ks * 16 + (l >> 4) * 8;
                unsigned addr = xs_base + row * XROWB + ((((colh >> 3) ^ (row & 7))) << 4);
                LDSM_X4(a[mf][0], a[mf][1], a[mf][2], a[mf][3], addr);
            }
            unsigned b[NFRAG][2];
#pragma unroll
            for (int g2 = 0; g2 < NFRAG / 2; g2++) {
                int brow = ks * 16 + (l & 15);
                int bcol = warp_n * WN + g2 * 16 + (l >> 4) * 8;
                unsigned addr = ws_base + brow * WROWB + ((((bcol >> 3) ^ (brow & 7))) << 4);
                unsigned r0, r1, r2, r3;
                LDSM_X4_T(r0, r1, r2, r3, addr);
                b[2 * g2][0] = r0; b[2 * g2][1] = r1;
                b[2 * g2 + 1][0] = r2; b[2 * g2 + 1][1] = r3;
            }
#pragma unroll
            for (int mf = 0; mf < 2; mf++)
#pragma unroll
                for (int nf = 0; nf < NFRAG; nf++)
                    MMA_16816(acc[mf][nf], a[mf], b[nf]);
        }

        // epilogue
        int g = l >> 2;
        int c2 = (l & 3) * 2;
#pragma unroll
        for (int mf = 0; mf < 2; mf++) {
            int r_lo = row0 + warp_m * 32 + mf * 16 + g;
            int r_hi = r_lo + 8;
            float di_lo = (r_lo < N) ? dinv[r_lo] : 0.f;
            float di_hi = (r_hi < N) ? dinv[r_hi] : 0.f;
#pragma unroll
            for (int nf = 0; nf < NFRAG; nf++) {
                int col = warp_n * WN + nf * 8 + c2;
                if (r_lo < N) {
                    __half2 h = __floats2half2_rn(di_lo * acc[mf][nf][0], di_lo * acc[mf][nf][1]);
                    *(__half2*)&Yh[(size_t)r_lo * FO + col] = h;
                }
                if (r_hi < N) {
                    __half2 h = __floats2half2_rn(di_hi * acc[mf][nf][2], di_hi * acc[mf][nf][3]);
                    *(__half2*)&Yh[(size_t)r_hi * FO + col] = h;
                }
            }
        }
        __syncthreads();   // all smem reads done before next tile's STS
    }
}

// ---------------- aggregation helpers ----------------
__device__ __forceinline__ void unpack_add8(uint4 u, float* acc) {
    float2 f;
    f = __half22float2(*(__half2*)&u.x); acc[0] += f.x; acc[1] += f.y;
    f = __half22float2(*(__half2*)&u.y); acc[2] += f.x; acc[3] += f.y;
    f = __half22float2(*(__half2*)&u.z); acc[4] += f.x; acc[5] += f.y;
    f = __half22float2(*(__half2*)&u.w); acc[6] += f.x; acc[7] += f.y;
}

// ---------------- agg + relu: warp per node, 2 edges/warp, 128 ch, fp16 out ----------------
__global__ void agg_relu128(const int* __restrict__ rowptr, const int* __restrict__ col,
                            const __half* __restrict__ Yh, const float* __restrict__ dinv,
                            const float* __restrict__ bias, __half* __restrict__ H, int N) {
    int node = (blockIdx.x * blockDim.x + threadIdx.x) >> 5;
    int lane = threadIdx.x & 31;
    if (node >= N) return;
    int hf = lane >> 4;
    int l16 = lane & 15;
    const uint4* Y4 = (const uint4*)Yh;

    float acc[8];
#pragma unroll
    for (int k = 0; k < 8; k++) acc[k] = 0.f;
    if (hf == 0)
        unpack_add8(Y4[(size_t)node * 16 + l16], acc);

    int end = rowptr[node + 1];
    int j = rowptr[node] + hf;
    for (; j + 2 < end; j += 4) {
        int s0 = __ldg(&col[j]);
        int s1 = __ldg(&col[j + 2]);
        uint4 a = Y4[(size_t)s0 * 16 + l16];
        uint4 b = Y4[(size_t)s1 * 16 + l16];
        unpack_add8(a, acc);
        unpack_add8(b, acc);
    }
    for (; j < end; j += 2) {
        int s = __ldg(&col[j]);
        unpack_add8(Y4[(size_t)s * 16 + l16], acc);
    }
#pragma unroll
    for (int k = 0; k < 8; k++)
        acc[k] += __shfl_xor_sync(0xFFFFFFFFu, acc[k], 16);

    if (hf == 0) {
        float di = dinv[node];
        float4 b0 = ((const float4*)bias)[l16 * 2];
        float4 b1 = ((const float4*)bias)[l16 * 2 + 1];
        __half2 p0 = __floats2half2_rn(fmaxf(fmaf(di, acc[0], b0.x), 0.f),
                                       fmaxf(fmaf(di, acc[1], b0.y), 0.f));
        __half2 p1 = __floats2half2_rn(fmaxf(fmaf(di, acc[2], b0.z), 0.f),
                                       fmaxf(fmaf(di, acc[3], b0.w), 0.f));
        __half2 p2 = __floats2half2_rn(fmaxf(fmaf(di, acc[4], b1.x), 0.f),
                                       fmaxf(fmaf(di, acc[5], b1.y), 0.f));
        __half2 p3 = __floats2half2_rn(fmaxf(fmaf(di, acc[6], b1.z), 0.f),
                                       fmaxf(fmaf(di, acc[7], b1.w), 0.f));
        uint4 u;
        u.x = *(unsigned*)&p0;
        u.y = *(unsigned*)&p1;
        u.z = *(unsigned*)&p2;
        u.w = *(unsigned*)&p3;
        ((uint4*)H)[(size_t)node * 16 + l16] = u;
    }
}

// ---------------- agg + log_softmax: warp per node, 64 ch ----------------
__global__ void agg_lsm64(const int* __restrict__ rowptr, const int* __restrict__ col,
                          const __half* __restrict__ Yh, const float* __restrict__ dinv,
                          const float* __restrict__ bias, float2* __restrict__ Out, int N) {
    int node = (blockIdx.x * blockDim.x + threadIdx.x) >> 5;
    int lane = threadIdx.x & 31;
    if (node >= N) return;
    const unsigned* Y1 = (const unsigned*)Yh;
    float2 acc;
    {
        unsigned u = Y1[(size_t)node * 32 + lane];
        acc = __half22float2(*(__half2*)&u);
    }
    int j = rowptr[node];
    int end = rowptr[node + 1];
    for (; j + 4 <= end; j += 4) {
        int s0 = __ldg(&col[j]);
        int s1 = __ldg(&col[j + 1]);
        int s2 = __ldg(&col[j + 2]);
        int s3 = __ldg(&col[j + 3]);
        unsigned u0 = Y1[(size_t)s0 * 32 + lane];
        unsigned u1 = Y1[(size_t)s1 * 32 + lane];
        unsigned u2 = Y1[(size_t)s2 * 32 + lane];
        unsigned u3 = Y1[(size_t)s3 * 32 + lane];
        float2 v0 = __half22float2(*(__half2*)&u0);
        float2 v1 = __half22float2(*(__half2*)&u1);
        float2 v2 = __half22float2(*(__half2*)&u2);
        float2 v3 = __half22float2(*(__half2*)&u3);
        acc.x += v0.x + v1.x + v2.x + v3.x;
        acc.y += v0.y + v1.y + v2.y + v3.y;
    }
    for (; j < end; j++) {
        int s = __ldg(&col[j]);
        unsigned u = Y1[(size_t)s * 32 + lane];
        float2 v = __half22float2(*(__half2*)&u);
        acc.x += v.x; acc.y += v.y;
    }
    float di = dinv[node];
    float2 b = ((const float2*)bias)[lane];
    float vx = fmaf(di, acc.x, b.x);
    float vy = fmaf(di, acc.y, b.y);
    float m = fmaxf(vx, vy);
#pragma unroll
    for (int o = 16; o > 0; o >>= 1)
        m = fmaxf(m, __shfl_xor_sync(0xFFFFFFFFu, m, o));
    float s = expf(vx - m) + expf(vy - m);
#pragma unroll
    for (int o = 16; o > 0; o >>= 1)
        s += __shfl_xor_sync(0xFFFFFFFFu, s, o);
    float ls = m + logf(s);
    float2 o2;
    o2.x = vx - ls;
    o2.y = vy - ls;
    Out[(size_t)node * 32 + lane] = o2;
}

// ---------------- driver ----------------
extern "C" void kernel_launch(void* const* d_in, const int* in_sizes, int n_in,
                              void* d_out, int out_size) {
    const float* x   = (const float*)d_in[0];
    const int*   ei  = (const int*)d_in[1];
    const float* W1  = (const float*)d_in[2];
    const float* b1  = (const float*)d_in[3];
    const float* W2  = (const float*)d_in[4];
    const float* b2  = (const float*)d_in[5];
    const float* W3  = (const float*)d_in[6];
    const float* b3  = (const float*)d_in[7];
    float* out = (float*)d_out;

    int N = in_sizes[0] / 128;
    int E = in_sizes[1] / 2;
    const int* src = ei;
    const int* dst = ei + E;

    __half *yh, *h;
    float* dinv;
    int *cnt, *excl, *bsum, *rowptr, *cursor, *col;
    cudaGetSymbolAddress((void**)&yh, g_yh);
    cudaGetSymbolAddress((void**)&h, g_h);
    cudaGetSymbolAddress((void**)&dinv, g_dinv);
    cudaGetSymbolAddress((void**)&cnt, g_cnt);
    cudaGetSymbolAddress((void**)&excl, g_excl);
    cudaGetSymbolAddress((void**)&bsum, g_bsum);
    cudaGetSymbolAddress((void**)&rowptr, g_rowptr);
    cudaGetSymbolAddress((void**)&cursor, g_cursor);
    cudaGetSymbolAddress((void**)&col, g_col);

    constexpr int SMEM128 = 128 * 256 + 128 * 256;  // 65536
    constexpr int SMEM64  = 128 * 256 + 128 * 128;  // 49152
    cudaFuncSetAttribute(gemm_hmma<128, true>,  cudaFuncAttributeMaxDynamicSharedMemorySize, SMEM128);
    cudaFuncSetAttribute(gemm_hmma<128, false>, cudaFuncAttributeMaxDynamicSharedMemorySize, SMEM128);
    cudaFuncSetAttribute(gemm_hmma<64, false>,  cudaFuncAttributeMaxDynamicSharedMemorySize, SMEM64);

    int nb_nodes = (N + 255) / 256;
    int nb_edges = (E + 255) / 256;
    int nb_scan  = (N + 1023) / 1024;
    int tiles = (N + 127) / 128;
    int gemm_blocks = tiles < 296 ? tiles : 296;   // persistent: 2 CTAs/SM
    int agg_blocks  = ((size_t)N * 32 + 255) / 256;

    // launch order: gemm1 is the 4th launch (profiler capture slot)
    zero_cnt<<<nb_nodes, 256>>>(cnt, N);                                      // 1
    count_deg<<<nb_edges, 256>>>(dst, cnt, E, N);                             // 2
    scan_block_dinv<<<nb_scan, 1024>>>(cnt, excl, bsum, dinv, N);             // 3
    gemm_hmma<128, true><<<gemm_blocks, 256, SMEM128>>>(x, W1, dinv, yh, N);  // 4 <- profiled
    scan_partials<<<1, 128>>>(bsum, nb_scan);                                 // 5
    scan_finish<<<(N + 256) / 256, 256>>>(excl, bsum, rowptr, cursor, N, E);  // 6
    fill_csr<<<nb_edges, 256>>>(src, dst, cursor, col, E, N);                 // 7

    // ---- layer 1 aggregation ----
    agg_relu128<<<agg_blocks, 256>>>(rowptr, col, yh, dinv, b1, h, N);
    // ---- layer 2 ----
    gemm_hmma<128, false><<<gemm_blocks, 256, SMEM128>>>(h, W2, dinv, yh, N);
    agg_relu128<<<agg_blocks, 256>>>(rowptr, col, yh, dinv, b2, h, N);
    // ---- layer 3 ----
    gemm_hmma<64, false><<<gemm_blocks, 256, SMEM64>>>(h, W3, dinv, yh, N);
    agg_lsm64<<<agg_blocks, 256>>>(rowptr, col, yh, dinv, b3, (float2*)out, N);
}

// round 8
// speedup vs baseline: 1.1614x; 1.0444x over previous
#include <cuda_runtime.h>
#include <cuda_fp16.h>
#include <math.h>
#include <stdint.h>

#define NN 100000
#define NE 1600000

// ---------------- scratch (device globals) ----------------
__device__ __half g_yh[(size_t)NN * 128];
__device__ __half g_h[(size_t)NN * 128];
__device__ float  g_dinv[NN];
__device__ int    g_cnt[NN];
__device__ int    g_excl[NN];
__device__ int    g_bsum[128];
__device__ int    g_rowptr[NN + 1];
__device__ int    g_cursor[NN];
__device__ int    g_col[NE];

// ---------------- prep ----------------
__global__ void zero_cnt(int* cnt, int n) {
    int i = blockIdx.x * blockDim.x + threadIdx.x;
    if (i < n) cnt[i] = 0;
}

__global__ void count_deg(const int* __restrict__ dst, int* __restrict__ cnt, int E, int N) {
    int e = blockIdx.x * blockDim.x + threadIdx.x;
    if (e >= E) return;
    int d = dst[e];
    if ((unsigned)d < (unsigned)N) atomicAdd(&cnt[d], 1);
}

__global__ void calc_dinv(const int* __restrict__ cnt, float* __restrict__ dinv, int n) {
    int i = blockIdx.x * blockDim.x + threadIdx.x;
    if (i < n) dinv[i] = rsqrtf((float)(cnt[i] + 1));
}

__global__ void scan_block(const int* __restrict__ cnt, int* __restrict__ excl,
                           int* __restrict__ bsum, int n) {
    __shared__ int sh[1024];
    int tid = threadIdx.x;
    int i = blockIdx.x * 1024 + tid;
    int v = (i < n) ? cnt[i] : 0;
    sh[tid] = v;
    __syncthreads();
#pragma unroll
    for (int off = 1; off < 1024; off <<= 1) {
        int t = (tid >= off) ? sh[tid - off] : 0;
        __syncthreads();
        sh[tid] += t;
        __syncthreads();
    }
    if (i < n) excl[i] = sh[tid] - v;
    if (tid == 1023) bsum[blockIdx.x] = sh[1023];
}

__global__ void scan_partials(int* bsum, int nb) {
    __shared__ int sh[128];
    int tid = threadIdx.x;
    int v = (tid < nb) ? bsum[tid] : 0;
    sh[tid] = v;
    __syncthreads();
#pragma unroll
    for (int off = 1; off < 128; off <<= 1) {
        int t = (tid >= off) ? sh[tid - off] : 0;
        __syncthreads();
        sh[tid] += t;
        __syncthreads();
    }
    if (tid < nb) bsum[tid] = sh[tid] - v;
}

__global__ void scan_finish(const int* __restrict__ excl, const int* __restrict__ bsum,
                            int* __restrict__ rowptr, int* __restrict__ cursor, int n, int E) {
    int i = blockIdx.x * blockDim.x + threadIdx.x;
    if (i < n) {
        int v = excl[i] + bsum[i >> 10];
        rowptr[i] = v;
        cursor[i] = v;
    } else if (i == n) {
        rowptr[n] = E;
    }
}

__global__ void fill_csr(const int* __restrict__ src, const int* __restrict__ dst,
                         int* __restrict__ cursor, int* __restrict__ col, int E, int N) {
    int e = blockIdx.x * blockDim.x + threadIdx.x;
    if (e >= E) return;
    int d = dst[e];
    if ((unsigned)d >= (unsigned)N) return;
    int p = atomicAdd(&cursor[d], 1);
    col[p] = src[e];
}

// ---------------- MMA / LDSM / cp.async macros ----------------
#define LDSM_X4(r0, r1, r2, r3, addr) \
    asm volatile("ldmatrix.sync.aligned.m8n8.x4.shared.b16 {%0,%1,%2,%3}, [%4];" \
                 : "=r"(r0), "=r"(r1), "=r"(r2), "=r"(r3) : "r"(addr))
#define LDSM_X4_T(r0, r1, r2, r3, addr) \
    asm volatile("ldmatrix.sync.aligned.m8n8.x4.trans.shared.b16 {%0,%1,%2,%3}, [%4];" \
                 : "=r"(r0), "=r"(r1), "=r"(r2), "=r"(r3) : "r"(addr))
#define MMA_16816(d, a, b) \
    asm volatile("mma.sync.aligned.m16n8k16.row.col.f32.f16.f16.f32 " \
                 "{%0,%1,%2,%3}, {%4,%5,%6,%7}, {%8,%9}, {%0,%1,%2,%3};" \
                 : "+f"(d[0]), "+f"(d[1]), "+f"(d[2]), "+f"(d[3]) \
                 : "r"(a[0]), "r"(a[1]), "r"(a[2]), "r"(a[3]), "r"(b[0]), "r"(b[1]))
#define CP_ASYNC16(dst, src) \
    asm volatile("cp.async.cg.shared.global [%0], [%1], 16;" :: "r"(dst), "l"(src))
#define CP_ASYNC16_Z(dst, src) \
    asm volatile("cp.async.cg.shared.global [%0], [%1], 16, 0;" :: "r"(dst), "l"(src))
#define CP_COMMIT() asm volatile("cp.async.commit_group;")
#define CP_WAIT(n)  asm volatile("cp.async.wait_group %0;" :: "n"(n))

// stage W (fp32 -> fp16, swizzled) — shared by both gemm kernels
template <int FO>
__device__ __forceinline__ void stage_w(const float* __restrict__ W, char* Ws, int tid) {
    constexpr int WROWB = FO * 2;
    for (int i = tid; i < 128 * FO / 4; i += 256) {
        int k = i / (FO / 4);
        int c4 = i % (FO / 4);
        float4 v = ((const float4*)W)[(size_t)k * (FO / 4) + c4];
        __half2 h0 = __floats2half2_rn(v.x, v.y);
        __half2 h1 = __floats2half2_rn(v.z, v.w);
        uint2 u;
        u.x = *(unsigned*)&h0;
        u.y = *(unsigned*)&h1;
        int chunk = c4 >> 1;
        *(uint2*)&Ws[k * WROWB + (((chunk ^ (k & 7)) << 4) | ((c4 & 1) << 3))] = u;
    }
}

// shared mainloop + epilogue
template <int FO>
__device__ __forceinline__ void tile_compute(unsigned xs_base, unsigned ws_base,
                                             const float* __restrict__ dinv,
                                             __half* __restrict__ Yh, int row0, int N,
                                             int warp_m, int warp_n, int l) {
    constexpr int WN = FO / 2;
    constexpr int NFRAG = WN / 8;
    constexpr int XROWB = 256;
    constexpr int WROWB = FO * 2;

    float acc[2][NFRAG][4];
#pragma unroll
    for (int mf = 0; mf < 2; mf++)
#pragma unroll
        for (int nf = 0; nf < NFRAG; nf++)
#pragma unroll
            for (int c = 0; c < 4; c++) acc[mf][nf][c] = 0.f;

#pragma unroll
    for (int ks = 0; ks < 8; ks++) {
        unsigned a[2][4];
#pragma unroll
        for (int mf = 0; mf < 2; mf++) {
            int row = warp_m * 32 + mf * 16 + (l & 15);
            int colh = ks * 16 + (l >> 4) * 8;
            unsigned addr = xs_base + row * XROWB + ((((colh >> 3) ^ (row & 7))) << 4);
            LDSM_X4(a[mf][0], a[mf][1], a[mf][2], a[mf][3], addr);
        }
        unsigned b[NFRAG][2];
#pragma unroll
        for (int g2 = 0; g2 < NFRAG / 2; g2++) {
            int brow = ks * 16 + (l & 15);
            int bcol = warp_n * WN + g2 * 16 + (l >> 4) * 8;
            unsigned addr = ws_base + brow * WROWB + ((((bcol >> 3) ^ (brow & 7))) << 4);
            unsigned r0, r1, r2, r3;
            LDSM_X4_T(r0, r1, r2, r3, addr);
            b[2 * g2][0] = r0; b[2 * g2][1] = r1;
            b[2 * g2 + 1][0] = r2; b[2 * g2 + 1][1] = r3;
        }
#pragma unroll
        for (int mf = 0; mf < 2; mf++)
#pragma unroll
            for (int nf = 0; nf < NFRAG; nf++)
                MMA_16816(acc[mf][nf], a[mf], b[nf]);
    }

    int g = l >> 2;
    int c2 = (l & 3) * 2;
#pragma unroll
    for (int mf = 0; mf < 2; mf++) {
        int r_lo = row0 + warp_m * 32 + mf * 16 + g;
        int r_hi = r_lo + 8;
        float di_lo = (r_lo < N) ? dinv[r_lo] : 0.f;
        float di_hi = (r_hi < N) ? dinv[r_hi] : 0.f;
#pragma unroll
        for (int nf = 0; nf < NFRAG; nf++) {
            int col = warp_n * WN + nf * 8 + c2;
            if (r_lo < N) {
                __half2 h = __floats2half2_rn(di_lo * acc[mf][nf][0], di_lo * acc[mf][nf][1]);
                *(__half2*)&Yh[(size_t)r_lo * FO + col] = h;
            }
            if (r_hi < N) {
                __half2 h = __floats2half2_rn(di_hi * acc[mf][nf][2], di_hi * acc[mf][nf][3]);
                *(__half2*)&Yh[(size_t)r_hi * FO + col] = h;
            }
        }
    }
}

// ---------------- gemm1: fp32 input, register-prefetch pipeline ----------------
__launch_bounds__(256, 2)
__global__ void gemm_hmma_f32(const float* __restrict__ Xin, const float* __restrict__ W,
                              const float* __restrict__ dinv, __half* __restrict__ Yh, int N) {
    constexpr int FO = 128;
    constexpr int BM = 128;
    constexpr int XROWB = 256;

    extern __shared__ char sm[];
    char* Xs = sm;
    char* Ws = sm + BM * XROWB;

    int tid = threadIdx.x;
    int warp = tid >> 5;
    int l = tid & 31;
    int warp_m = warp & 3;
    int warp_n = warp >> 2;

    stage_w<FO>(W, Ws, tid);

    unsigned xs_base = (unsigned)__cvta_generic_to_shared(Xs);
    unsigned ws_base = (unsigned)__cvta_generic_to_shared(Ws);

    int tiles = (N + BM - 1) / BM;
    int t = blockIdx.x;
    uint4 pf[8];

    auto ldg_tile = [&](int row0) {
#pragma unroll
        for (int j = 0; j < 8; j++) {
            int i = tid + j * 256;
            int r = i >> 4;
            int q = i & 15;
            int gr = row0 + r;
            uint4 v = make_uint4(0, 0, 0, 0);
            if (gr < N) {
                const float4* p = (const float4*)Xin + (size_t)gr * 32 + q * 2;
                float4 f0 = p[0];
                float4 f1 = p[1];
                __half2 h0 = __floats2half2_rn(f0.x, f0.y);
                __half2 h1 = __floats2half2_rn(f0.z, f0.w);
                __half2 h2 = __floats2half2_rn(f1.x, f1.y);
                __half2 h3 = __floats2half2_rn(f1.z, f1.w);
                v.x = *(unsigned*)&h0;
                v.y = *(unsigned*)&h1;
                v.z = *(unsigned*)&h2;
                v.w = *(unsigned*)&h3;
            }
            pf[j] = v;
        }
    };

    if (t < tiles) ldg_tile(t * BM);

    for (; t < tiles; t += gridDim.x) {
        int row0 = t * BM;
#pragma unroll
        for (int j = 0; j < 8; j++) {
            int i = tid + j * 256;
            int r = i >> 4;
            int q = i & 15;
            *(uint4*)&Xs[r * XROWB + ((q ^ (r & 7)) << 4)] = pf[j];
        }
        __syncthreads();
        int tn = t + gridDim.x;
        if (tn < tiles) ldg_tile(tn * BM);
        tile_compute<FO>(xs_base, ws_base, dinv, Yh, row0, N, warp_m, warp_n, l);
        __syncthreads();
    }
}

// ---------------- gemm (fp16 input): cp.async double-buffered ----------------
template <int FO>
__launch_bounds__(256, 2)
__global__ void gemm_hmma_ca(const __half* __restrict__ Xin, const float* __restrict__ W,
                             const float* __restrict__ dinv, __half* __restrict__ Yh, int N) {
    constexpr int BM = 128;
    constexpr int XROWB = 256;
    constexpr int XBUF = BM * XROWB;     // 32 KB

    extern __shared__ char sm[];
    char* Xs = sm;                        // 2 buffers
    char* Ws = sm + 2 * XBUF;

    int tid = threadIdx.x;
    int warp = tid >> 5;
    int l = tid & 31;
    int warp_m = warp & 3;
    int warp_n = warp >> 2;

    stage_w<FO>(W, Ws, tid);

    unsigned xs_base0 = (unsigned)__cvta_generic_to_shared(Xs);
    unsigned ws_base = (unsigned)__cvta_generic_to_shared(Ws);

    int tiles = (N + BM - 1) / BM;
    int t = blockIdx.x;

    auto stage_x = [&](int tile, int buf) {
        int row0 = tile * BM;
        unsigned base = xs_base0 + buf * XBUF;
#pragma unroll
        for (int j = 0; j < 8; j++) {
            int i = tid + j * 256;
            int r = i >> 4;
            int q = i & 15;
            int gr = row0 + r;
            unsigned dst = base + r * XROWB + ((q ^ (r & 7)) << 4);
            const __half* src = Xin + (size_t)(gr < N ? gr : 0) * 128 + q * 8;
            if (gr < N) CP_ASYNC16(dst, src);
            else        CP_ASYNC16_Z(dst, src);
        }
        CP_COMMIT();
    };

    int buf = 0;
    if (t < tiles) stage_x(t, 0);

    for (; t < tiles; t += gridDim.x) {
        int tn = t + gridDim.x;
        if (tn < tiles) {
            stage_x(tn, buf ^ 1);
            CP_WAIT(1);
        } else {
            CP_WAIT(0);
        }
        __syncthreads();
        tile_compute<FO>(xs_base0 + buf * XBUF, ws_base, dinv, Yh, t * BM, N,
                         warp_m, warp_n, l);
        __syncthreads();
        buf ^= 1;
    }
}

// ---------------- aggregation helpers ----------------
__device__ __forceinline__ void unpack_add8(uint4 u, float* acc) {
    float2 f;
    f = __half22float2(*(__half2*)&u.x); acc[0] += f.x; acc[1] += f.y;
    f = __half22float2(*(__half2*)&u.y); acc[2] += f.x; acc[3] += f.y;
    f = __half22float2(*(__half2*)&u.z); acc[4] += f.x; acc[5] += f.y;
    f = __half22float2(*(__half2*)&u.w); acc[6] += f.x; acc[7] += f.y;
}

__global__ void agg_relu128(const int* __restrict__ rowptr, const int* __restrict__ col,
                            const __half* __restrict__ Yh, const float* __restrict__ dinv,
                            const float* __restrict__ bias, __half* __restrict__ H, int N) {
    int node = (blockIdx.x * blockDim.x + threadIdx.x) >> 5;
    int lane = threadIdx.x & 31;
    if (node >= N) return;
    int hf = lane >> 4;
    int l16 = lane & 15;
    const uint4* Y4 = (const uint4*)Yh;

    float acc[8];
#pragma unroll
    for (int k = 0; k < 8; k++) acc[k] = 0.f;
    if (hf == 0)
        unpack_add8(Y4[(size_t)node * 16 + l16], acc);

    int end = rowptr[node + 1];
    int j = rowptr[node] + hf;
    for (; j + 2 < end; j += 4) {
        int s0 = __ldg(&col[j]);
        int s1 = __ldg(&col[j + 2]);
        uint4 a = Y4[(size_t)s0 * 16 + l16];
        uint4 b = Y4[(size_t)s1 * 16 + l16];
        unpack_add8(a, acc);
        unpack_add8(b, acc);
    }
    for (; j < end; j += 2) {
        int s = __ldg(&col[j]);
        unpack_add8(Y4[(size_t)s * 16 + l16], acc);
    }
#pragma unroll
    for (int k = 0; k < 8; k++)
        acc[k] += __shfl_xor_sync(0xFFFFFFFFu, acc[k], 16);

    if (hf == 0) {
        float di = dinv[node];
        float4 b0 = ((const float4*)bias)[l16 * 2];
        float4 b1 = ((const float4*)bias)[l16 * 2 + 1];
        __half2 p0 = __floats2half2_rn(fmaxf(fmaf(di, acc[0], b0.x), 0.f),
                                       fmaxf(fmaf(di, acc[1], b0.y), 0.f));
        __half2 p1 = __floats2half2_rn(fmaxf(fmaf(di, acc[2], b0.z), 0.f),
                                       fmaxf(fmaf(di, acc[3], b0.w), 0.f));
        __half2 p2 = __floats2half2_rn(fmaxf(fmaf(di, acc[4], b1.x), 0.f),
                                       fmaxf(fmaf(di, acc[5], b1.y), 0.f));
        __half2 p3 = __floats2half2_rn(fmaxf(fmaf(di, acc[6], b1.z), 0.f),
                                       fmaxf(fmaf(di, acc[7], b1.w), 0.f));
        uint4 u;
        u.x = *(unsigned*)&p0;
        u.y = *(unsigned*)&p1;
        u.z = *(unsigned*)&p2;
        u.w = *(unsigned*)&p3;
        ((uint4*)H)[(size_t)node * 16 + l16] = u;
    }
}

__global__ void agg_lsm64(const int* __restrict__ rowptr, const int* __restrict__ col,
                          const __half* __restrict__ Yh, const float* __restrict__ dinv,
                          const float* __restrict__ bias, float2* __restrict__ Out, int N) {
    int node = (blockIdx.x * blockDim.x + threadIdx.x) >> 5;
    int lane = threadIdx.x & 31;
    if (node >= N) return;
    const unsigned* Y1 = (const unsigned*)Yh;
    float2 acc;
    {
        unsigned u = Y1[(size_t)node * 32 + lane];
        acc = __half22float2(*(__half2*)&u);
    }
    int j = rowptr[node];
    int end = rowptr[node + 1];
    for (; j + 4 <= end; j += 4) {
        int s0 = __ldg(&col[j]);
        int s1 = __ldg(&col[j + 1]);
        int s2 = __ldg(&col[j + 2]);
        int s3 = __ldg(&col[j + 3]);
        unsigned u0 = Y1[(size_t)s0 * 32 + lane];
        unsigned u1 = Y1[(size_t)s1 * 32 + lane];
        unsigned u2 = Y1[(size_t)s2 * 32 + lane];
        unsigned u3 = Y1[(size_t)s3 * 32 + lane];
        float2 v0 = __half22float2(*(__half2*)&u0);
        float2 v1 = __half22float2(*(__half2*)&u1);
        float2 v2 = __half22float2(*(__half2*)&u2);
        float2 v3 = __half22float2(*(__half2*)&u3);
        acc.x += v0.x + v1.x + v2.x + v3.x;
        acc.y += v0.y + v1.y + v2.y + v3.y;
    }
    for (; j < end; j++) {
        int s = __ldg(&col[j]);
        unsigned u = Y1[(size_t)s * 32 + lane];
        float2 v = __half22float2(*(__half2*)&u);
        acc.x += v.x; acc.y += v.y;
    }
    float di = dinv[node];
    float2 b = ((const float2*)bias)[lane];
    float vx = fmaf(di, acc.x, b.x);
    float vy = fmaf(di, acc.y, b.y);
    float m = fmaxf(vx, vy);
#pragma unroll
    for (int o = 16; o > 0; o >>= 1)
        m = fmaxf(m, __shfl_xor_sync(0xFFFFFFFFu, m, o));
    float s = expf(vx - m) + expf(vy - m);
#pragma unroll
    for (int o = 16; o > 0; o >>= 1)
        s += __shfl_xor_sync(0xFFFFFFFFu, s, o);
    float ls = m + logf(s);
    float2 o2;
    o2.x = vx - ls;
    o2.y = vy - ls;
    Out[(size_t)node * 32 + lane] = o2;
}

// ---------------- driver ----------------
extern "C" void kernel_launch(void* const* d_in, const int* in_sizes, int n_in,
                              void* d_out, int out_size) {
    const float* x   = (const float*)d_in[0];
    const int*   ei  = (const int*)d_in[1];
    const float* W1  = (const float*)d_in[2];
    const float* b1  = (const float*)d_in[3];
    const float* W2  = (const float*)d_in[4];
    const float* b2  = (const float*)d_in[5];
    const float* W3  = (const float*)d_in[6];
    const float* b3  = (const float*)d_in[7];
    float* out = (float*)d_out;

    int N = in_sizes[0] / 128;
    int E = in_sizes[1] / 2;
    const int* src = ei;
    const int* dst = ei + E;

    __half *yh, *h;
    float* dinv;
    int *cnt, *excl, *bsum, *rowptr, *cursor, *col;
    cudaGetSymbolAddress((void**)&yh, g_yh);
    cudaGetSymbolAddress((void**)&h, g_h);
    cudaGetSymbolAddress((void**)&dinv, g_dinv);
    cudaGetSymbolAddress((void**)&cnt, g_cnt);
    cudaGetSymbolAddress((void**)&excl, g_excl);
    cudaGetSymbolAddress((void**)&bsum, g_bsum);
    cudaGetSymbolAddress((void**)&rowptr, g_rowptr);
    cudaGetSymbolAddress((void**)&cursor, g_cursor);
    cudaGetSymbolAddress((void**)&col, g_col);

    // one-time side stream + events (resource creation only; identical work per call)
    static cudaStream_t s_side = 0;
    static cudaEvent_t ev_fork = 0, ev_join = 0;
    static bool inited = false;
    if (!inited) {
        inited = true;
        if (cudaStreamCreateWithFlags(&s_side, cudaStreamNonBlocking) != cudaSuccess)
            s_side = 0;
        if (s_side) {
            if (cudaEventCreateWithFlags(&ev_fork, cudaEventDisableTiming) != cudaSuccess ||
                cudaEventCreateWithFlags(&ev_join, cudaEventDisableTiming) != cudaSuccess) {
                s_side = 0;
            }
        }
    }
    bool fork = (s_side != 0);
    cudaStream_t sc = fork ? s_side : 0;   // CSR-chain stream

    constexpr int SMEM_G1  = 128 * 256 + 128 * 256;      // 64 KB
    constexpr int SMEM_CA128 = 2 * 32768 + 128 * 256;    // 96 KB
    constexpr int SMEM_CA64  = 2 * 32768 + 128 * 128;    // 80 KB
    cudaFuncSetAttribute(gemm_hmma_f32,     cudaFuncAttributeMaxDynamicSharedMemorySize, SMEM_G1);
    cudaFuncSetAttribute(gemm_hmma_ca<128>, cudaFuncAttributeMaxDynamicSharedMemorySize, SMEM_CA128);
    cudaFuncSetAttribute(gemm_hmma_ca<64>,  cudaFuncAttributeMaxDynamicSharedMemorySize, SMEM_CA64);

    int nb_nodes = (N + 255) / 256;
    int nb_edges = (E + 255) / 256;
    int nb_scan  = (N + 1023) / 1024;
    int tiles = (N + 127) / 128;
    int gemm_blocks = tiles < 296 ? tiles : 296;
    int agg_blocks  = ((size_t)N * 32 + 255) / 256;

    // ---- serial prefix on default stream: degree + dinv ----
    zero_cnt<<<nb_nodes, 256>>>(cnt, N);                                   // 1
    count_deg<<<nb_edges, 256>>>(dst, cnt, E, N);                          // 2
    calc_dinv<<<nb_nodes, 256>>>(cnt, dinv, N);                            // 3

    // ---- fork: gemm1 on default || CSR chain on side stream ----
    if (fork) cudaEventRecord(ev_fork, 0);
    gemm_hmma_f32<<<gemm_blocks, 256, SMEM_G1>>>(x, W1, dinv, yh, N);      // 4 <- profiled
    if (fork) cudaStreamWaitEvent(s_side, ev_fork, 0);
    scan_block<<<nb_scan, 1024, 0, sc>>>(cnt, excl, bsum, N);
    scan_partials<<<1, 128, 0, sc>>>(bsum, nb_scan);
    scan_finish<<<(N + 256) / 256, 256, 0, sc>>>(excl, bsum, rowptr, cursor, N, E);
    fill_csr<<<nb_edges, 256, 0, sc>>>(src, dst, cursor, col, E, N);
    if (fork) {
        cudaEventRecord(ev_join, s_side);
        cudaStreamWaitEvent(0, ev_join, 0);
    }

    // ---- layer 1 aggregation ----
    agg_relu128<<<agg_blocks, 256>>>(rowptr, col, yh, dinv, b1, h, N);
    // ---- layer 2 ----
    gemm_hmma_ca<128><<<gemm_blocks, 256, SMEM_CA128>>>(h, W2, dinv, yh, N);
    agg_relu128<<<agg_blocks, 256>>>(rowptr, col, yh, dinv, b2, h, N);
    // ---- layer 3 ----
    gemm_hmma_ca<64><<<gemm_blocks, 256, SMEM_CA64>>>(h, W3, dinv, yh, N);
    agg_lsm64<<<agg_blocks, 256>>>(rowptr, col, yh, dinv, b3, (float2*)out, N);
}

// round 10
// speedup vs baseline: 1.1652x; 1.0034x over previous
#include <cuda_runtime.h>
#include <cuda_fp16.h>
#include <math.h>
#include <stdint.h>

#define NN 100000
#define NE 1600000

// ---------------- scratch (device globals) ----------------
__device__ __half g_yh[(size_t)NN * 128];
__device__ __half g_h[(size_t)NN * 128];
__device__ float  g_dinv[NN];
__device__ int    g_cnt[NN];
__device__ int    g_excl[NN];
__device__ int    g_bsum[128];
__device__ int    g_rowptr[NN + 1];
__device__ int    g_cursor[NN];
__device__ int    g_col[NE];

// ---------------- prep ----------------
__global__ void zero_cnt(int* cnt, int n) {
    int i = blockIdx.x * blockDim.x + threadIdx.x;
    if (i < n) cnt[i] = 0;
}

__global__ void count_deg(const int* __restrict__ dst, int* __restrict__ cnt, int E, int N) {
    int e = blockIdx.x * blockDim.x + threadIdx.x;
    if (e >= E) return;
    int d = dst[e];
    if ((unsigned)d < (unsigned)N) atomicAdd(&cnt[d], 1);
}

__global__ void scan_block_dinv(const int* __restrict__ cnt, int* __restrict__ excl,
                                int* __restrict__ bsum, float* __restrict__ dinv, int n) {
    __shared__ int sh[1024];
    int tid = threadIdx.x;
    int i = blockIdx.x * 1024 + tid;
    int v = (i < n) ? cnt[i] : 0;
    if (i < n) dinv[i] = rsqrtf((float)(v + 1));
    sh[tid] = v;
    __syncthreads();
#pragma unroll
    for (int off = 1; off < 1024; off <<= 1) {
        int t = (tid >= off) ? sh[tid - off] : 0;
        __syncthreads();
        sh[tid] += t;
        __syncthreads();
    }
    if (i < n) excl[i] = sh[tid] - v;
    if (tid == 1023) bsum[blockIdx.x] = sh[1023];
}

__global__ void scan_partials(int* bsum, int nb) {
    __shared__ int sh[128];
    int tid = threadIdx.x;
    int v = (tid < nb) ? bsum[tid] : 0;
    sh[tid] = v;
    __syncthreads();
#pragma unroll
    for (int off = 1; off < 128; off <<= 1) {
        int t = (tid >= off) ? sh[tid - off] : 0;
        __syncthreads();
        sh[tid] += t;
        __syncthreads();
    }
    if (tid < nb) bsum[tid] = sh[tid] - v;
}

__global__ void scan_finish(const int* __restrict__ excl, const int* __restrict__ bsum,
                            int* __restrict__ rowptr, int* __restrict__ cursor, int n, int E) {
    int i = blockIdx.x * blockDim.x + threadIdx.x;
    if (i < n) {
        int v = excl[i] + bsum[i >> 10];
        rowptr[i] = v;
        cursor[i] = v;
    } else if (i == n) {
        rowptr[n] = E;
    }
}

__global__ void fill_csr(const int* __restrict__ src, const int* __restrict__ dst,
                         int* __restrict__ cursor, int* __restrict__ col, int E, int N) {
    int e = blockIdx.x * blockDim.x + threadIdx.x;
    if (e >= E) return;
    int d = dst[e];
    if ((unsigned)d >= (unsigned)N) return;
    int p = atomicAdd(&cursor[d], 1);
    col[p] = src[e];
}

// ---------------- MMA / LDSM / cp.async macros ----------------
#define LDSM_X4(r0, r1, r2, r3, addr) \
    asm volatile("ldmatrix.sync.aligned.m8n8.x4.shared.b16 {%0,%1,%2,%3}, [%4];" \
                 : "=r"(r0), "=r"(r1), "=r"(r2), "=r"(r3) : "r"(addr))
#define LDSM_X4_T(r0, r1, r2, r3, addr) \
    asm volatile("ldmatrix.sync.aligned.m8n8.x4.trans.shared.b16 {%0,%1,%2,%3}, [%4];" \
                 : "=r"(r0), "=r"(r1), "=r"(r2), "=r"(r3) : "r"(addr))
#define MMA_16816(d, a, b) \
    asm volatile("mma.sync.aligned.m16n8k16.row.col.f32.f16.f16.f32 " \
                 "{%0,%1,%2,%3}, {%4,%5,%6,%7}, {%8,%9}, {%0,%1,%2,%3};" \
                 : "+f"(d[0]), "+f"(d[1]), "+f"(d[2]), "+f"(d[3]) \
                 : "r"(a[0]), "r"(a[1]), "r"(a[2]), "r"(a[3]), "r"(b[0]), "r"(b[1]))
#define CP_ASYNC16(dst, src) \
    asm volatile("cp.async.cg.shared.global [%0], [%1], 16;" :: "r"(dst), "l"(src))
#define CP_ASYNC16_Z(dst, src) \
    asm volatile("cp.async.cg.shared.global [%0], [%1], 16, 0;" :: "r"(dst), "l"(src))
#define CP_COMMIT() asm volatile("cp.async.commit_group;")
#define CP_WAIT(n)  asm volatile("cp.async.wait_group %0;" :: "n"(n))

template <int FO>
__device__ __forceinline__ void stage_w(const float* __restrict__ W, char* Ws, int tid) {
    constexpr int WROWB = FO * 2;
    for (int i = tid; i < 128 * FO / 4; i += 256) {
        int k = i / (FO / 4);
        int c4 = i % (FO / 4);
        float4 v = ((const float4*)W)[(size_t)k * (FO / 4) + c4];
        __half2 h0 = __floats2half2_rn(v.x, v.y);
        __half2 h1 = __floats2half2_rn(v.z, v.w);
        uint2 u;
        u.x = *(unsigned*)&h0;
        u.y = *(unsigned*)&h1;
        int chunk = c4 >> 1;
        *(uint2*)&Ws[k * WROWB + (((chunk ^ (k & 7)) << 4) | ((c4 & 1) << 3))] = u;
    }
}

template <int FO, bool SCALE>
__device__ __forceinline__ void tile_compute(unsigned xs_base, unsigned ws_base,
                                             const float* __restrict__ dinv,
                                             __half* __restrict__ Yh, int row0, int N,
                                             int warp_m, int warp_n, int l) {
    constexpr int WN = FO / 2;
    constexpr int NFRAG = WN / 8;
    constexpr int XROWB = 256;
    constexpr int WROWB = FO * 2;

    float acc[2][NFRAG][4];
#pragma unroll
    for (int mf = 0; mf < 2; mf++)
#pragma unroll
        for (int nf = 0; nf < NFRAG; nf++)
#pragma unroll
            for (int c = 0; c < 4; c++) acc[mf][nf][c] = 0.f;

#pragma unroll
    for (int ks = 0; ks < 8; ks++) {
        unsigned a[2][4];
#pragma unroll
        for (int mf = 0; mf < 2; mf++) {
            int row = warp_m * 32 + mf * 16 + (l & 15);
            int colh = ks * 16 + (l >> 4) * 8;
            unsigned addr = xs_base + row * XROWB + ((((colh >> 3) ^ (row & 7))) << 4);
            LDSM_X4(a[mf][0], a[mf][1], a[mf][2], a[mf][3], addr);
        }
        unsigned b[NFRAG][2];
#pragma unroll
        for (int g2 = 0; g2 < NFRAG / 2; g2++) {
            int brow = ks * 16 + (l & 15);
            int bcol = warp_n * WN + g2 * 16 + (l >> 4) * 8;
            unsigned addr = ws_base + brow * WROWB + ((((bcol >> 3) ^ (brow & 7))) << 4);
            unsigned r0, r1, r2, r3;
            LDSM_X4_T(r0, r1, r2, r3, addr);
            b[2 * g2][0] = r0; b[2 * g2][1] = r1;
            b[2 * g2 + 1][0] = r2; b[2 * g2 + 1][1] = r3;
        }
#pragma unroll
        for (int mf = 0; mf < 2; mf++)
#pragma unroll
            for (int nf = 0; nf < NFRAG; nf++)
                MMA_16816(acc[mf][nf], a[mf], b[nf]);
    }

    int g = l >> 2;
    int c2 = (l & 3) * 2;
#pragma unroll
    for (int mf = 0; mf < 2; mf++) {
        int r_lo = row0 + warp_m * 32 + mf * 16 + g;
        int r_hi = r_lo + 8;
        float di_lo = 1.f, di_hi = 1.f;
        if (SCALE) {
            di_lo = (r_lo < N) ? dinv[r_lo] : 0.f;
            di_hi = (r_hi < N) ? dinv[r_hi] : 0.f;
        }
#pragma unroll
        for (int nf = 0; nf < NFRAG; nf++) {
            int col = warp_n * WN + nf * 8 + c2;
            if (r_lo < N) {
                __half2 h = SCALE ? __floats2half2_rn(di_lo * acc[mf][nf][0], di_lo * acc[mf][nf][1])
                                  : __floats2half2_rn(acc[mf][nf][0], acc[mf][nf][1]);
                *(__half2*)&Yh[(size_t)r_lo * FO + col] = h;
            }
            if (r_hi < N) {
                __half2 h = SCALE ? __floats2half2_rn(di_hi * acc[mf][nf][2], di_hi * acc[mf][nf][3])
                                  : __floats2half2_rn(acc[mf][nf][2], acc[mf][nf][3]);
                *(__half2*)&Yh[(size_t)r_hi * FO + col] = h;
            }
        }
    }
}

// ---------------- gemm1: fp32 input, UNSCALED output (no prep dependency) ----------------
__launch_bounds__(256, 2)
__global__ void gemm_hmma_f32(const float* __restrict__ Xin, const float* __restrict__ W,
                              __half* __restrict__ Yh, int N) {
    constexpr int FO = 128;
    constexpr int BM = 128;
    constexpr int XROWB = 256;

    extern __shared__ char sm[];
    char* Xs = sm;
    char* Ws = sm + BM * XROWB;

    int tid = threadIdx.x;
    int warp = tid >> 5;
    int l = tid & 31;
    int warp_m = warp & 3;
    int warp_n = warp >> 2;

    stage_w<FO>(W, Ws, tid);

    unsigned xs_base = (unsigned)__cvta_generic_to_shared(Xs);
    unsigned ws_base = (unsigned)__cvta_generic_to_shared(Ws);

    int tiles = (N + BM - 1) / BM;
    int t = blockIdx.x;
    uint4 pf[8];

    auto ldg_tile = [&](int row0) {
#pragma unroll
        for (int j = 0; j < 8; j++) {
            int i = tid + j * 256;
            int r = i >> 4;
            int q = i & 15;
            int gr = row0 + r;
            uint4 v = make_uint4(0, 0, 0, 0);
            if (gr < N) {
                const float4* p = (const float4*)Xin + (size_t)gr * 32 + q * 2;
                float4 f0 = p[0];
                float4 f1 = p[1];
                __half2 h0 = __floats2half2_rn(f0.x, f0.y);
                __half2 h1 = __floats2half2_rn(f0.z, f0.w);
                __half2 h2 = __floats2half2_rn(f1.x, f1.y);
                __half2 h3 = __floats2half2_rn(f1.z, f1.w);
                v.x = *(unsigned*)&h0;
                v.y = *(unsigned*)&h1;
                v.z = *(unsigned*)&h2;
                v.w = *(unsigned*)&h3;
            }
            pf[j] = v;
        }
    };

    if (t < tiles) ldg_tile(t * BM);

    for (; t < tiles; t += gridDim.x) {
        int row0 = t * BM;
#pragma unroll
        for (int j = 0; j < 8; j++) {
            int i = tid + j * 256;
            int r = i >> 4;
            int q = i & 15;
            *(uint4*)&Xs[r * XROWB + ((q ^ (r & 7)) << 4)] = pf[j];
        }
        __syncthreads();
        int tn = t + gridDim.x;
        if (tn < tiles) ldg_tile(tn * BM);
        tile_compute<FO, false>(xs_base, ws_base, nullptr, Yh, row0, N, warp_m, warp_n, l);
        __syncthreads();
    }
}

// ---------------- gemm fp16 input: cp.async double-buffered, SCALED output ----------------
template <int FO>
__launch_bounds__(256, 2)
__global__ void gemm_hmma_ca(const __half* __restrict__ Xin, const float* __restrict__ W,
                             const float* __restrict__ dinv, __half* __restrict__ Yh, int N) {
    constexpr int BM = 128;
    constexpr int XROWB = 256;
    constexpr int XBUF = BM * XROWB;

    extern __shared__ char sm[];
    char* Xs = sm;
    char* Ws = sm + 2 * XBUF;

    int tid = threadIdx.x;
    int warp = tid >> 5;
    int l = tid & 31;
    int warp_m = warp & 3;
    int warp_n = warp >> 2;

    stage_w<FO>(W, Ws, tid);

    unsigned xs_base0 = (unsigned)__cvta_generic_to_shared(Xs);
    unsigned ws_base = (unsigned)__cvta_generic_to_shared(Ws);

    int tiles = (N + BM - 1) / BM;
    int t = blockIdx.x;

    auto stage_x = [&](int tile, int buf) {
        int row0 = tile * BM;
        unsigned base = xs_base0 + buf * XBUF;
#pragma unroll
        for (int j = 0; j < 8; j++) {
            int i = tid + j * 256;
            int r = i >> 4;
            int q = i & 15;
            int gr = row0 + r;
            unsigned dst = base + r * XROWB + ((q ^ (r & 7)) << 4);
            const __half* src = Xin + (size_t)(gr < N ? gr : 0) * 128 + q * 8;
            if (gr < N) CP_ASYNC16(dst, src);
            else        CP_ASYNC16_Z(dst, src);
        }
        CP_COMMIT();
    };

    int buf = 0;
    if (t < tiles) stage_x(t, 0);

    for (; t < tiles; t += gridDim.x) {
        int tn = t + gridDim.x;
        if (tn < tiles) {
            stage_x(tn, buf ^ 1);
            CP_WAIT(1);
        } else {
            CP_WAIT(0);
        }
        __syncthreads();
        tile_compute<FO, true>(xs_base0 + buf * XBUF, ws_base, dinv, Yh, t * BM, N,
                               warp_m, warp_n, l);
        __syncthreads();
        buf ^= 1;
    }
}

// ---------------- aggregation helpers ----------------
__device__ __forceinline__ void unpack_add8(uint4 u, float* acc) {
    float2 f;
    f = __half22float2(*(__half2*)&u.x); acc[0] += f.x; acc[1] += f.y;
    f = __half22float2(*(__half2*)&u.y); acc[2] += f.x; acc[3] += f.y;
    f = __half22float2(*(__half2*)&u.z); acc[4] += f.x; acc[5] += f.y;
    f = __half22float2(*(__half2*)&u.w); acc[6] += f.x; acc[7] += f.y;
}
__device__ __forceinline__ void unpack_fma8(uint4 u, float s, float* acc) {
    float2 f;
    f = __half22float2(*(__half2*)&u.x); acc[0] = fmaf(s, f.x, acc[0]); acc[1] = fmaf(s, f.y, acc[1]);
    f = __half22float2(*(__half2*)&u.y); acc[2] = fmaf(s, f.x, acc[2]); acc[3] = fmaf(s, f.y, acc[3]);
    f = __half22float2(*(__half2*)&u.z); acc[4] = fmaf(s, f.x, acc[4]); acc[5] = fmaf(s, f.y, acc[5]);
    f = __half22float2(*(__half2*)&u.w); acc[6] = fmaf(s, f.x, acc[6]); acc[7] = fmaf(s, f.y, acc[7]);
}

// layer-1 agg: Y is UNSCALED -> multiply each gathered row by dinv[s]
__global__ void agg_relu128_l1(const int* __restrict__ rowptr, const int* __restrict__ col,
                               const __half* __restrict__ Yh, const float* __restrict__ dinv,
                               const float* __restrict__ bias, __half* __restrict__ H, int N) {
    int node = (blockIdx.x * blockDim.x + threadIdx.x) >> 5;
    int lane = threadIdx.x & 31;
    if (node >= N) return;
    int hf = lane >> 4;
    int l16 = lane & 15;
    const uint4* Y4 = (const uint4*)Yh;

    float di = dinv[node];
    float acc[8];
#pragma unroll
    for (int k = 0; k < 8; k++) acc[k] = 0.f;
    if (hf == 0)
        unpack_fma8(Y4[(size_t)node * 16 + l16], di, acc);

    int end = rowptr[node + 1];
    int j = rowptr[node] + hf;
    for (; j + 2 < end; j += 4) {
        int s0 = __ldg(&col[j]);
        int s1 = __ldg(&col[j + 2]);
        float d0 = __ldg(&dinv[s0]);
        float d1 = __ldg(&dinv[s1]);
        uint4 a = Y4[(size_t)s0 * 16 + l16];
        uint4 b = Y4[(size_t)s1 * 16 + l16];
        unpack_fma8(a, d0, acc);
        unpack_fma8(b, d1, acc);
    }
    for (; j < end; j += 2) {
        int s = __ldg(&col[j]);
        float ds = __ldg(&dinv[s]);
        unpack_fma8(Y4[(size_t)s * 16 + l16], ds, acc);
    }
#pragma unroll
    for (int k = 0; k < 8; k++)
        acc[k] += __shfl_xor_sync(0xFFFFFFFFu, acc[k], 16);

    if (hf == 0) {
        float4 b0 = ((const float4*)bias)[l16 * 2];
        float4 b1 = ((const float4*)bias)[l16 * 2 + 1];
        __half2 p0 = __floats2half2_rn(fmaxf(fmaf(di, acc[0], b0.x), 0.f),
                                       fmaxf(fmaf(di, acc[1], b0.y), 0.f));
        __half2 p1 = __floats2half2_rn(fmaxf(fmaf(di, acc[2], b0.z), 0.f),
                                       fmaxf(fmaf(di, acc[3], b0.w), 0.f));
        __half2 p2 = __floats2half2_rn(fmaxf(fmaf(di, acc[4], b1.x), 0.f),
                                       fmaxf(fmaf(di, acc[5], b1.y), 0.f));
        __half2 p3 = __floats2half2_rn(fmaxf(fmaf(di, acc[6], b1.z), 0.f),
                                       fmaxf(fmaf(di, acc[7], b1.w), 0.f));
        uint4 u;
        u.x = *(unsigned*)&p0;
        u.y = *(unsigned*)&p1;
        u.z = *(unsigned*)&p2;
        u.w = *(unsigned*)&p3;
        ((uint4*)H)[(size_t)node * 16 + l16] = u;
    }
}

// layer 2: Y pre-scaled
__global__ void agg_relu128(const int* __restrict__ rowptr, const int* __restrict__ col,
                            const __half* __restrict__ Yh, const float* __restrict__ dinv,
                            const float* __restrict__ bias, __half* __restrict__ H, int N) {
    int node = (blockIdx.x * blockDim.x + threadIdx.x) >> 5;
    int lane = threadIdx.x & 31;
    if (node >= N) return;
    int hf = lane >> 4;
    int l16 = lane & 15;
    const uint4* Y4 = (const uint4*)Yh;

    float acc[8];
#pragma unroll
    for (int k = 0; k < 8; k++) acc[k] = 0.f;
    if (hf == 0)
        unpack_add8(Y4[(size_t)node * 16 + l16], acc);

    int end = rowptr[node + 1];
    int j = rowptr[node] + hf;
    for (; j + 2 < end; j += 4) {
        int s0 = __ldg(&col[j]);
        int s1 = __ldg(&col[j + 2]);
        uint4 a = Y4[(size_t)s0 * 16 + l16];
        uint4 b = Y4[(size_t)s1 * 16 + l16];
        unpack_add8(a, acc);
        unpack_add8(b, acc);
    }
    for (; j < end; j += 2) {
        int s = __ldg(&col[j]);
        unpack_add8(Y4[(size_t)s * 16 + l16], acc);
    }
#pragma unroll
    for (int k = 0; k < 8; k++)
        acc[k] += __shfl_xor_sync(0xFFFFFFFFu, acc[k], 16);

    if (hf == 0) {
        float di = dinv[node];
        float4 b0 = ((const float4*)bias)[l16 * 2];
        float4 b1 = ((const float4*)bias)[l16 * 2 + 1];
        __half2 p0 = __floats2half2_rn(fmaxf(fmaf(di, acc[0], b0.x), 0.f),
                                       fmaxf(fmaf(di, acc[1], b0.y), 0.f));
        __half2 p1 = __floats2half2_rn(fmaxf(fmaf(di, acc[2], b0.z), 0.f),
                                       fmaxf(fmaf(di, acc[3], b0.w), 0.f));
        __half2 p2 = __floats2half2_rn(fmaxf(fmaf(di, acc[4], b1.x), 0.f),
                                       fmaxf(fmaf(di, acc[5], b1.y), 0.f));
        __half2 p3 = __floats2half2_rn(fmaxf(fmaf(di, acc[6], b1.z), 0.f),
                                       fmaxf(fmaf(di, acc[7], b1.w), 0.f));
        uint4 u;
        u.x = *(unsigned*)&p0;
        u.y = *(unsigned*)&p1;
        u.z = *(unsigned*)&p2;
        u.w = *(unsigned*)&p3;
        ((uint4*)H)[(size_t)node * 16 + l16] = u;
    }
}

// layer 3: half-warp edges + log_softmax over 64 ch
__global__ void agg_lsm64(const int* __restrict__ rowptr, const int* __restrict__ col,
                          const __half* __restrict__ Yh, const float* __restrict__ dinv,
                          const float* __restrict__ bias, float4* __restrict__ Out, int N) {
    int node = (blockIdx.x * blockDim.x + threadIdx.x) >> 5;
    int lane = threadIdx.x & 31;
    if (node >= N) return;
    int hf = lane >> 4;
    int l16 = lane & 15;
    const uint2* Y2 = (const uint2*)Yh;

    float acc[4];
#pragma unroll
    for (int k = 0; k < 4; k++) acc[k] = 0.f;
    if (hf == 0) {
        uint2 u = Y2[(size_t)node * 16 + l16];
        float2 f;
        f = __half22float2(*(__half2*)&u.x); acc[0] += f.x; acc[1] += f.y;
        f = __half22float2(*(__half2*)&u.y); acc[2] += f.x; acc[3] += f.y;
    }
    int end = rowptr[node + 1];
    int j = rowptr[node] + hf;
    for (; j + 2 < end; j += 4) {
        int s0 = __ldg(&col[j]);
        int s1 = __ldg(&col[j + 2]);
        uint2 a = Y2[(size_t)s0 * 16 + l16];
        uint2 b = Y2[(size_t)s1 * 16 + l16];
        float2 f;
        f = __half22float2(*(__half2*)&a.x); acc[0] += f.x; acc[1] += f.y;
        f = __half22float2(*(__half2*)&a.y); acc[2] += f.x; acc[3] += f.y;
        f = __half22float2(*(__half2*)&b.x); acc[0] += f.x; acc[1] += f.y;
        f = __half22float2(*(__half2*)&b.y); acc[2] += f.x; acc[3] += f.y;
    }
    for (; j < end; j += 2) {
        int s = __ldg(&col[j]);
        uint2 a = Y2[(size_t)s * 16 + l16];
        float2 f;
        f = __half22float2(*(__half2*)&a.x); acc[0] += f.x; acc[1] += f.y;
        f = __half22float2(*(__half2*)&a.y); acc[2] += f.x; acc[3] += f.y;
    }
#pragma unroll
    for (int k = 0; k < 4; k++)
        acc[k] += __shfl_xor_sync(0xFFFFFFFFu, acc[k], 16);

    float di = dinv[node];
    float4 b = ((const float4*)bias)[l16];
    float v0 = fmaf(di, acc[0], b.x);
    float v1 = fmaf(di, acc[1], b.y);
    float v2 = fmaf(di, acc[2], b.z);
    float v3 = fmaf(di, acc[3], b.w);
    float m = fmaxf(fmaxf(v0, v1), fmaxf(v2, v3));
#pragma unroll
    for (int o = 8; o > 0; o >>= 1)
        m = fmaxf(m, __shfl_xor_sync(0xFFFFFFFFu, m, o));
    float s = expf(v0 - m) + expf(v1 - m) + expf(v2 - m) + expf(v3 - m);
#pragma unroll
    for (int o = 8; o > 0; o >>= 1)
        s += __shfl_xor_sync(0xFFFFFFFFu, s, o);
    float ls = m + logf(s);
    if (hf == 0)
        Out[(size_t)node * 16 + l16] = make_float4(v0 - ls, v1 - ls, v2 - ls, v3 - ls);
}

// ---------------- driver ----------------
extern "C" void kernel_launch(void* const* d_in, const int* in_sizes, int n_in,
                              void* d_out, int out_size) {
    const float* x   = (const float*)d_in[0];
    const int*   ei  = (const int*)d_in[1];
    const float* W1  = (const float*)d_in[2];
    const float* b1  = (const float*)d_in[3];
    const float* W2  = (const float*)d_in[4];
    const float* b2  = (const float*)d_in[5];
    const float* W3  = (const float*)d_in[6];
    const float* b3  = (const float*)d_in[7];
    float* out = (float*)d_out;

    int N = in_sizes[0] / 128;
    int E = in_sizes[1] / 2;
    const int* src = ei;
    const int* dst = ei + E;

    __half *yh, *h;
    float* dinv;
    int *cnt, *excl, *bsum, *rowptr, *cursor, *col;
    cudaGetSymbolAddress((void**)&yh, g_yh);
    cudaGetSymbolAddress((void**)&h, g_h);
    cudaGetSymbolAddress((void**)&dinv, g_dinv);
    cudaGetSymbolAddress((void**)&cnt, g_cnt);
    cudaGetSymbolAddress((void**)&excl, g_excl);
    cudaGetSymbolAddress((void**)&bsum, g_bsum);
    cudaGetSymbolAddress((void**)&rowptr, g_rowptr);
    cudaGetSymbolAddress((void**)&cursor, g_cursor);
    cudaGetSymbolAddress((void**)&col, g_col);

    static cudaStream_t s_side = 0;
    static cudaEvent_t ev_fork = 0, ev_join = 0;
    static bool inited = false;
    if (!inited) {
        inited = true;
        if (cudaStreamCreateWithFlags(&s_side, cudaStreamNonBlocking) != cudaSuccess)
            s_side = 0;
        if (s_side) {
            if (cudaEventCreateWithFlags(&ev_fork, cudaEventDisableTiming) != cudaSuccess ||
                cudaEventCreateWithFlags(&ev_join, cudaEventDisableTiming) != cudaSuccess)
                s_side = 0;
        }
    }
    bool fork = (s_side != 0);
    cudaStream_t sc = fork ? s_side : 0;

    constexpr int SMEM_G1    = 128 * 256 + 128 * 256;    // 64 KB
    constexpr int SMEM_CA128 = 2 * 32768 + 128 * 256;    // 96 KB
    constexpr int SMEM_CA64  = 2 * 32768 + 128 * 128;    // 80 KB
    cudaFuncSetAttribute(gemm_hmma_f32,     cudaFuncAttributeMaxDynamicSharedMemorySize, SMEM_G1);
    cudaFuncSetAttribute(gemm_hmma_ca<128>, cudaFuncAttributeMaxDynamicSharedMemorySize, SMEM_CA128);
    cudaFuncSetAttribute(gemm_hmma_ca<64>,  cudaFuncAttributeMaxDynamicSharedMemorySize, SMEM_CA64);

    int nb_nodes = (N + 255) / 256;
    int nb_edges = (E + 255) / 256;
    int nb_scan  = (N + 1023) / 1024;
    int tiles = (N + 127) / 128;
    int gemm_blocks = tiles < 296 ? tiles : 296;
    int agg_blocks  = ((size_t)N * 32 + 255) / 256;

    // ---- fork FROM the capture-origin stream, then prep || gemm1 ----
    if (fork) {
        cudaEventRecord(ev_fork, 0);                 // capture-origin edge
        cudaStreamWaitEvent(s_side, ev_fork, 0);     // side stream joins capture
    }
    zero_cnt<<<nb_nodes, 256, 0, sc>>>(cnt, N);
    count_deg<<<nb_edges, 256, 0, sc>>>(dst, cnt, E, N);
    scan_block_dinv<<<nb_scan, 1024, 0, sc>>>(cnt, excl, bsum, dinv, N);
    gemm_hmma_f32<<<gemm_blocks, 256, SMEM_G1>>>(x, W1, yh, N);   // default stream, no deps
    scan_partials<<<1, 128, 0, sc>>>(bsum, nb_scan);
    scan_finish<<<(N + 256) / 256, 256, 0, sc>>>(excl, bsum, rowptr, cursor, N, E);
    fill_csr<<<nb_edges, 256, 0, sc>>>(src, dst, cursor, col, E, N);
    if (fork) {
        cudaEventRecord(ev_join, s_side);
        cudaStreamWaitEvent(0, ev_join, 0);
    }

    // ---- layer 1 aggregation (applies dinv[s] per edge) ----
    agg_relu128_l1<<<agg_blocks, 256>>>(rowptr, col, yh, dinv, b1, h, N);
    // ---- layer 2 ----
    gemm_hmma_ca<128><<<gemm_blocks, 256, SMEM_CA128>>>(h, W2, dinv, yh, N);
    agg_relu128<<<agg_blocks, 256>>>(rowptr, col, yh, dinv, b2, h, N);
    // ---- layer 3 ----
    gemm_hmma_ca<64><<<gemm_blocks, 256, SMEM_CA64>>>(h, W3, dinv, yh, N);
    agg_lsm64<<<agg_blocks, 256>>>(rowptr, col, yh, dinv, b3, (float4*)out, N);
}

// round 11
// speedup vs baseline: 1.1773x; 1.0103x over previous
#include <cuda_runtime.h>
#include <cuda_fp16.h>
#include <math.h>
#include <stdint.h>

#define NN 100000
#define NE 1600000

// ---------------- scratch (device globals) ----------------
__device__ __half g_yh[(size_t)NN * 128];
__device__ __half g_h[(size_t)NN * 128];
__device__ float  g_dinv[NN];
__device__ int    g_cnt[NN];
__device__ int    g_excl[NN];
__device__ int    g_bsum[128];
__device__ int    g_rowptr[NN + 1];
__device__ int    g_cursor[NN];
__device__ int    g_col[NE];

// ---------------- prep ----------------
__global__ void zero_cnt(int* cnt, int n) {
    int i = blockIdx.x * blockDim.x + threadIdx.x;
    if (i < n) cnt[i] = 0;
}

__global__ void count_deg(const int* __restrict__ dst, int* __restrict__ cnt, int E, int N) {
    int e = blockIdx.x * blockDim.x + threadIdx.x;
    if (e >= E) return;
    int d = dst[e];
    if ((unsigned)d < (unsigned)N) atomicAdd(&cnt[d], 1);
}

__global__ void scan_block_dinv(const int* __restrict__ cnt, int* __restrict__ excl,
                                int* __restrict__ bsum, float* __restrict__ dinv, int n) {
    __shared__ int sh[1024];
    int tid = threadIdx.x;
    int i = blockIdx.x * 1024 + tid;
    int v = (i < n) ? cnt[i] : 0;
    if (i < n) dinv[i] = rsqrtf((float)(v + 1));
    sh[tid] = v;
    __syncthreads();
#pragma unroll
    for (int off = 1; off < 1024; off <<= 1) {
        int t = (tid >= off) ? sh[tid - off] : 0;
        __syncthreads();
        sh[tid] += t;
        __syncthreads();
    }
    if (i < n) excl[i] = sh[tid] - v;
    if (tid == 1023) bsum[blockIdx.x] = sh[1023];
}

__global__ void scan_partials(int* bsum, int nb) {
    __shared__ int sh[128];
    int tid = threadIdx.x;
    int v = (tid < nb) ? bsum[tid] : 0;
    sh[tid] = v;
    __syncthreads();
#pragma unroll
    for (int off = 1; off < 128; off <<= 1) {
        int t = (tid >= off) ? sh[tid - off] : 0;
        __syncthreads();
        sh[tid] += t;
        __syncthreads();
    }
    if (tid < nb) bsum[tid] = sh[tid] - v;
}

__global__ void scan_finish(const int* __restrict__ excl, const int* __restrict__ bsum,
                            int* __restrict__ rowptr, int* __restrict__ cursor, int n, int E) {
    int i = blockIdx.x * blockDim.x + threadIdx.x;
    if (i < n) {
        int v = excl[i] + bsum[i >> 10];
        rowptr[i] = v;
        cursor[i] = v;
    } else if (i == n) {
        rowptr[n] = E;
    }
}

__global__ void fill_csr(const int* __restrict__ src, const int* __restrict__ dst,
                         int* __restrict__ cursor, int* __restrict__ col, int E, int N) {
    int e = blockIdx.x * blockDim.x + threadIdx.x;
    if (e >= E) return;
    int d = dst[e];
    if ((unsigned)d >= (unsigned)N) return;
    int p = atomicAdd(&cursor[d], 1);
    col[p] = src[e];
}

// ---------------- MMA / LDSM / cp.async macros ----------------
#define LDSM_X4(r0, r1, r2, r3, addr) \
    asm volatile("ldmatrix.sync.aligned.m8n8.x4.shared.b16 {%0,%1,%2,%3}, [%4];" \
                 : "=r"(r0), "=r"(r1), "=r"(r2), "=r"(r3) : "r"(addr))
#define LDSM_X4_T(r0, r1, r2, r3, addr) \
    asm volatile("ldmatrix.sync.aligned.m8n8.x4.trans.shared.b16 {%0,%1,%2,%3}, [%4];" \
                 : "=r"(r0), "=r"(r1), "=r"(r2), "=r"(r3) : "r"(addr))
#define MMA_16816(d, a, b) \
    asm volatile("mma.sync.aligned.m16n8k16.row.col.f32.f16.f16.f32 " \
                 "{%0,%1,%2,%3}, {%4,%5,%6,%7}, {%8,%9}, {%0,%1,%2,%3};" \
                 : "+f"(d[0]), "+f"(d[1]), "+f"(d[2]), "+f"(d[3]) \
                 : "r"(a[0]), "r"(a[1]), "r"(a[2]), "r"(a[3]), "r"(b[0]), "r"(b[1]))
#define CP_ASYNC16(dst, src) \
    asm volatile("cp.async.cg.shared.global [%0], [%1], 16;" :: "r"(dst), "l"(src))
#define CP_ASYNC16_Z(dst, src) \
    asm volatile("cp.async.cg.shared.global [%0], [%1], 16, 0;" :: "r"(dst), "l"(src))
#define CP_COMMIT() asm volatile("cp.async.commit_group;")
#define CP_WAIT(n)  asm volatile("cp.async.wait_group %0;" :: "n"(n))

template <int FO>
__device__ __forceinline__ void stage_w(const float* __restrict__ W, char* Ws, int tid) {
    constexpr int WROWB = FO * 2;
    for (int i = tid; i < 128 * FO / 4; i += 256) {
        int k = i / (FO / 4);
        int c4 = i % (FO / 4);
        float4 v = ((const float4*)W)[(size_t)k * (FO / 4) + c4];
        __half2 h0 = __floats2half2_rn(v.x, v.y);
        __half2 h1 = __floats2half2_rn(v.z, v.w);
        uint2 u;
        u.x = *(unsigned*)&h0;
        u.y = *(unsigned*)&h1;
        int chunk = c4 >> 1;
        *(uint2*)&Ws[k * WROWB + (((chunk ^ (k & 7)) << 4) | ((c4 & 1) << 3))] = u;
    }
}

template <int FO, bool SCALE>
__device__ __forceinline__ void tile_compute(unsigned xs_base, unsigned ws_base,
                                             const float* __restrict__ dinv,
                                             __half* __restrict__ Yh, int row0, int N,
                                             int warp_m, int warp_n, int l) {
    constexpr int WN = FO / 2;
    constexpr int NFRAG = WN / 8;
    constexpr int XROWB = 256;
    constexpr int WROWB = FO * 2;

    float acc[2][NFRAG][4];
#pragma unroll
    for (int mf = 0; mf < 2; mf++)
#pragma unroll
        for (int nf = 0; nf < NFRAG; nf++)
#pragma unroll
            for (int c = 0; c < 4; c++) acc[mf][nf][c] = 0.f;

#pragma unroll
    for (int ks = 0; ks < 8; ks++) {
        unsigned a[2][4];
#pragma unroll
        for (int mf = 0; mf < 2; mf++) {
            int row = warp_m * 32 + mf * 16 + (l & 15);
            int colh = ks * 16 + (l >> 4) * 8;
            unsigned addr = xs_base + row * XROWB + ((((colh >> 3) ^ (row & 7))) << 4);
            LDSM_X4(a[mf][0], a[mf][1], a[mf][2], a[mf][3], addr);
        }
        unsigned b[NFRAG][2];
#pragma unroll
        for (int g2 = 0; g2 < NFRAG / 2; g2++) {
            int brow = ks * 16 + (l & 15);
            int bcol = warp_n * WN + g2 * 16 + (l >> 4) * 8;
            unsigned addr = ws_base + brow * WROWB + ((((bcol >> 3) ^ (brow & 7))) << 4);
            unsigned r0, r1, r2, r3;
            LDSM_X4_T(r0, r1, r2, r3, addr);
            b[2 * g2][0] = r0; b[2 * g2][1] = r1;
            b[2 * g2 + 1][0] = r2; b[2 * g2 + 1][1] = r3;
        }
#pragma unroll
        for (int mf = 0; mf < 2; mf++)
#pragma unroll
            for (int nf = 0; nf < NFRAG; nf++)
                MMA_16816(acc[mf][nf], a[mf], b[nf]);
    }

    int g = l >> 2;
    int c2 = (l & 3) * 2;
#pragma unroll
    for (int mf = 0; mf < 2; mf++) {
        int r_lo = row0 + warp_m * 32 + mf * 16 + g;
        int r_hi = r_lo + 8;
        float di_lo = 1.f, di_hi = 1.f;
        if (SCALE) {
            di_lo = (r_lo < N) ? dinv[r_lo] : 0.f;
            di_hi = (r_hi < N) ? dinv[r_hi] : 0.f;
        }
#pragma unroll
        for (int nf = 0; nf < NFRAG; nf++) {
            int col = warp_n * WN + nf * 8 + c2;
            if (r_lo < N) {
                __half2 h = SCALE ? __floats2half2_rn(di_lo * acc[mf][nf][0], di_lo * acc[mf][nf][1])
                                  : __floats2half2_rn(acc[mf][nf][0], acc[mf][nf][1]);
                *(__half2*)&Yh[(size_t)r_lo * FO + col] = h;
            }
            if (r_hi < N) {
                __half2 h = SCALE ? __floats2half2_rn(di_hi * acc[mf][nf][2], di_hi * acc[mf][nf][3])
                                  : __floats2half2_rn(acc[mf][nf][2], acc[mf][nf][3]);
                *(__half2*)&Yh[(size_t)r_hi * FO + col] = h;
            }
        }
    }
}

// ---------------- gemm1: fp32 input, UNSCALED output ----------------
__launch_bounds__(256, 2)
__global__ void gemm_hmma_f32(const float* __restrict__ Xin, const float* __restrict__ W,
                              __half* __restrict__ Yh, int N) {
    constexpr int FO = 128;
    constexpr int BM = 128;
    constexpr int XROWB = 256;

    extern __shared__ char sm[];
    char* Xs = sm;
    char* Ws = sm + BM * XROWB;

    int tid = threadIdx.x;
    int warp = tid >> 5;
    int l = tid & 31;
    int warp_m = warp & 3;
    int warp_n = warp >> 2;

    stage_w<FO>(W, Ws, tid);

    unsigned xs_base = (unsigned)__cvta_generic_to_shared(Xs);
    unsigned ws_base = (unsigned)__cvta_generic_to_shared(Ws);

    int tiles = (N + BM - 1) / BM;
    int t = blockIdx.x;
    uint4 pf[8];

    auto ldg_tile = [&](int row0) {
#pragma unroll
        for (int j = 0; j < 8; j++) {
            int i = tid + j * 256;
            int r = i >> 4;
            int q = i & 15;
            int gr = row0 + r;
            uint4 v = make_uint4(0, 0, 0, 0);
            if (gr < N) {
                const float4* p = (const float4*)Xin + (size_t)gr * 32 + q * 2;
                float4 f0 = p[0];
                float4 f1 = p[1];
                __half2 h0 = __floats2half2_rn(f0.x, f0.y);
                __half2 h1 = __floats2half2_rn(f0.z, f0.w);
                __half2 h2 = __floats2half2_rn(f1.x, f1.y);
                __half2 h3 = __floats2half2_rn(f1.z, f1.w);
                v.x = *(unsigned*)&h0;
                v.y = *(unsigned*)&h1;
                v.z = *(unsigned*)&h2;
                v.w = *(unsigned*)&h3;
            }
            pf[j] = v;
        }
    };

    if (t < tiles) ldg_tile(t * BM);

    for (; t < tiles; t += gridDim.x) {
        int row0 = t * BM;
#pragma unroll
        for (int j = 0; j < 8; j++) {
            int i = tid + j * 256;
            int r = i >> 4;
            int q = i & 15;
            *(uint4*)&Xs[r * XROWB + ((q ^ (r & 7)) << 4)] = pf[j];
        }
        __syncthreads();
        int tn = t + gridDim.x;
        if (tn < tiles) ldg_tile(tn * BM);
        tile_compute<FO, false>(xs_base, ws_base, nullptr, Yh, row0, N, warp_m, warp_n, l);
        __syncthreads();
    }
}

// ---------------- gemm fp16 input: cp.async double-buffered, SCALED output ----------------
template <int FO>
__launch_bounds__(256, 2)
__global__ void gemm_hmma_ca(const __half* __restrict__ Xin, const float* __restrict__ W,
                             const float* __restrict__ dinv, __half* __restrict__ Yh, int N) {
    constexpr int BM = 128;
    constexpr int XROWB = 256;
    constexpr int XBUF = BM * XROWB;

    extern __shared__ char sm[];
    char* Xs = sm;
    char* Ws = sm + 2 * XBUF;

    int tid = threadIdx.x;
    int warp = tid >> 5;
    int l = tid & 31;
    int warp_m = warp & 3;
    int warp_n = warp >> 2;

    stage_w<FO>(W, Ws, tid);

    unsigned xs_base0 = (unsigned)__cvta_generic_to_shared(Xs);
    unsigned ws_base = (unsigned)__cvta_generic_to_shared(Ws);

    int tiles = (N + BM - 1) / BM;
    int t = blockIdx.x;

    auto stage_x = [&](int tile, int buf) {
        int row0 = tile * BM;
        unsigned base = xs_base0 + buf * XBUF;
#pragma unroll
        for (int j = 0; j < 8; j++) {
            int i = tid + j * 256;
            int r = i >> 4;
            int q = i & 15;
            int gr = row0 + r;
            unsigned dst = base + r * XROWB + ((q ^ (r & 7)) << 4);
            const __half* src = Xin + (size_t)(gr < N ? gr : 0) * 128 + q * 8;
            if (gr < N) CP_ASYNC16(dst, src);
            else        CP_ASYNC16_Z(dst, src);
        }
        CP_COMMIT();
    };

    int buf = 0;
    if (t < tiles) stage_x(t, 0);

    for (; t < tiles; t += gridDim.x) {
        int tn = t + gridDim.x;
        if (tn < tiles) {
            stage_x(tn, buf ^ 1);
            CP_WAIT(1);
        } else {
            CP_WAIT(0);
        }
        __syncthreads();
        tile_compute<FO, true>(xs_base0 + buf * XBUF, ws_base, dinv, Yh, t * BM, N,
                               warp_m, warp_n, l);
        __syncthreads();
        buf ^= 1;
    }
}

// ---------------- aggregation helpers ----------------
__device__ __forceinline__ void unpack_add8(uint4 u, float* acc) {
    float2 f;
    f = __half22float2(*(__half2*)&u.x); acc[0] += f.x; acc[1] += f.y;
    f = __half22float2(*(__half2*)&u.y); acc[2] += f.x; acc[3] += f.y;
    f = __half22float2(*(__half2*)&u.z); acc[4] += f.x; acc[5] += f.y;
    f = __half22float2(*(__half2*)&u.w); acc[6] += f.x; acc[7] += f.y;
}
__device__ __forceinline__ void unpack_fma8(uint4 u, float s, float* acc) {
    float2 f;
    f = __half22float2(*(__half2*)&u.x); acc[0] = fmaf(s, f.x, acc[0]); acc[1] = fmaf(s, f.y, acc[1]);
    f = __half22float2(*(__half2*)&u.y); acc[2] = fmaf(s, f.x, acc[2]); acc[3] = fmaf(s, f.y, acc[3]);
    f = __half22float2(*(__half2*)&u.z); acc[4] = fmaf(s, f.x, acc[4]); acc[5] = fmaf(s, f.y, acc[5]);
    f = __half22float2(*(__half2*)&u.w); acc[6] = fmaf(s, f.x, acc[6]); acc[7] = fmaf(s, f.y, acc[7]);
}
__device__ __forceinline__ void unpack_add4(uint2 u, float* acc) {
    float2 f;
    f = __half22float2(*(__half2*)&u.x); acc[0] += f.x; acc[1] += f.y;
    f = __half22float2(*(__half2*)&u.y); acc[2] += f.x; acc[3] += f.y;
}

// layer-1 agg: Y UNSCALED -> dinv[s] per edge; 4 edges in flight per half-warp
__global__ void agg_relu128_l1(const int* __restrict__ rowptr, const int* __restrict__ col,
                               const __half* __restrict__ Yh, const float* __restrict__ dinv,
                               const float* __restrict__ bias, __half* __restrict__ H, int N) {
    int node = (blockIdx.x * blockDim.x + threadIdx.x) >> 5;
    int lane = threadIdx.x & 31;
    if (node >= N) return;
    int hf = lane >> 4;
    int l16 = lane & 15;
    const uint4* Y4 = (const uint4*)Yh;

    float di = dinv[node];
    float acc[8];
#pragma unroll
    for (int k = 0; k < 8; k++) acc[k] = 0.f;
    if (hf == 0)
        unpack_fma8(Y4[(size_t)node * 16 + l16], di, acc);

    int end = rowptr[node + 1];
    int j = rowptr[node] + hf;
    for (; j + 6 < end; j += 8) {
        int s0 = __ldg(&col[j]);
        int s1 = __ldg(&col[j + 2]);
        int s2 = __ldg(&col[j + 4]);
        int s3 = __ldg(&col[j + 6]);
        float d0 = __ldg(&dinv[s0]);
        float d1 = __ldg(&dinv[s1]);
        float d2 = __ldg(&dinv[s2]);
        float d3 = __ldg(&dinv[s3]);
        uint4 a = Y4[(size_t)s0 * 16 + l16];
        uint4 b = Y4[(size_t)s1 * 16 + l16];
        uint4 c = Y4[(size_t)s2 * 16 + l16];
        uint4 d = Y4[(size_t)s3 * 16 + l16];
        unpack_fma8(a, d0, acc);
        unpack_fma8(b, d1, acc);
        unpack_fma8(c, d2, acc);
        unpack_fma8(d, d3, acc);
    }
    for (; j + 2 < end; j += 4) {
        int s0 = __ldg(&col[j]);
        int s1 = __ldg(&col[j + 2]);
        float d0 = __ldg(&dinv[s0]);
        float d1 = __ldg(&dinv[s1]);
        uint4 a = Y4[(size_t)s0 * 16 + l16];
        uint4 b = Y4[(size_t)s1 * 16 + l16];
        unpack_fma8(a, d0, acc);
        unpack_fma8(b, d1, acc);
    }
    for (; j < end; j += 2) {
        int s = __ldg(&col[j]);
        float ds = __ldg(&dinv[s]);
        unpack_fma8(Y4[(size_t)s * 16 + l16], ds, acc);
    }
#pragma unroll
    for (int k = 0; k < 8; k++)
        acc[k] += __shfl_xor_sync(0xFFFFFFFFu, acc[k], 16);

    if (hf == 0) {
        float4 b0 = ((const float4*)bias)[l16 * 2];
        float4 b1 = ((const float4*)bias)[l16 * 2 + 1];
        __half2 p0 = __floats2half2_rn(fmaxf(fmaf(di, acc[0], b0.x), 0.f),
                                       fmaxf(fmaf(di, acc[1], b0.y), 0.f));
        __half2 p1 = __floats2half2_rn(fmaxf(fmaf(di, acc[2], b0.z), 0.f),
                                       fmaxf(fmaf(di, acc[3], b0.w), 0.f));
        __half2 p2 = __floats2half2_rn(fmaxf(fmaf(di, acc[4], b1.x), 0.f),
                                       fmaxf(fmaf(di, acc[5], b1.y), 0.f));
        __half2 p3 = __floats2half2_rn(fmaxf(fmaf(di, acc[6], b1.z), 0.f),
                                       fmaxf(fmaf(di, acc[7], b1.w), 0.f));
        uint4 u;
        u.x = *(unsigned*)&p0;
        u.y = *(unsigned*)&p1;
        u.z = *(unsigned*)&p2;
        u.w = *(unsigned*)&p3;
        ((uint4*)H)[(size_t)node * 16 + l16] = u;
    }
}

// layer 2: Y pre-scaled; 4 edges in flight per half-warp
__global__ void agg_relu128(const int* __restrict__ rowptr, const int* __restrict__ col,
                            const __half* __restrict__ Yh, const float* __restrict__ dinv,
                            const float* __restrict__ bias, __half* __restrict__ H, int N) {
    int node = (blockIdx.x * blockDim.x + threadIdx.x) >> 5;
    int lane = threadIdx.x & 31;
    if (node >= N) return;
    int hf = lane >> 4;
    int l16 = lane & 15;
    const uint4* Y4 = (const uint4*)Yh;

    float acc[8];
#pragma unroll
    for (int k = 0; k < 8; k++) acc[k] = 0.f;
    if (hf == 0)
        unpack_add8(Y4[(size_t)node * 16 + l16], acc);

    int end = rowptr[node + 1];
    int j = rowptr[node] + hf;
    for (; j + 6 < end; j += 8) {
        int s0 = __ldg(&col[j]);
        int s1 = __ldg(&col[j + 2]);
        int s2 = __ldg(&col[j + 4]);
        int s3 = __ldg(&col[j + 6]);
        uint4 a = Y4[(size_t)s0 * 16 + l16];
        uint4 b = Y4[(size_t)s1 * 16 + l16];
        uint4 c = Y4[(size_t)s2 * 16 + l16];
        uint4 d = Y4[(size_t)s3 * 16 + l16];
        unpack_add8(a, acc);
        unpack_add8(b, acc);
        unpack_add8(c, acc);
        unpack_add8(d, acc);
    }
    for (; j + 2 < end; j += 4) {
        int s0 = __ldg(&col[j]);
        int s1 = __ldg(&col[j + 2]);
        uint4 a = Y4[(size_t)s0 * 16 + l16];
        uint4 b = Y4[(size_t)s1 * 16 + l16];
        unpack_add8(a, acc);
        unpack_add8(b, acc);
    }
    for (; j < end; j += 2) {
        int s = __ldg(&col[j]);
        unpack_add8(Y4[(size_t)s * 16 + l16], acc);
    }
#pragma unroll
    for (int k = 0; k < 8; k++)
        acc[k] += __shfl_xor_sync(0xFFFFFFFFu, acc[k], 16);

    if (hf == 0) {
        float di = dinv[node];
        float4 b0 = ((const float4*)bias)[l16 * 2];
        float4 b1 = ((const float4*)bias)[l16 * 2 + 1];
        __half2 p0 = __floats2half2_rn(fmaxf(fmaf(di, acc[0], b0.x), 0.f),
                                       fmaxf(fmaf(di, acc[1], b0.y), 0.f));
        __half2 p1 = __floats2half2_rn(fmaxf(fmaf(di, acc[2], b0.z), 0.f),
                                       fmaxf(fmaf(di, acc[3], b0.w), 0.f));
        __half2 p2 = __floats2half2_rn(fmaxf(fmaf(di, acc[4], b1.x), 0.f),
                                       fmaxf(fmaf(di, acc[5], b1.y), 0.f));
        __half2 p3 = __floats2half2_rn(fmaxf(fmaf(di, acc[6], b1.z), 0.f),
                                       fmaxf(fmaf(di, acc[7], b1.w), 0.f));
        uint4 u;
        u.x = *(unsigned*)&p0;
        u.y = *(unsigned*)&p1;
        u.z = *(unsigned*)&p2;
        u.w = *(unsigned*)&p3;
        ((uint4*)H)[(size_t)node * 16 + l16] = u;
    }
}

// layer 3: half-warp edges, 4 in flight, + log_softmax over 64 ch
__global__ void agg_lsm64(const int* __restrict__ rowptr, const int* __restrict__ col,
                          const __half* __restrict__ Yh, const float* __restrict__ dinv,
                          const float* __restrict__ bias, float4* __restrict__ Out, int N) {
    int node = (blockIdx.x * blockDim.x + threadIdx.x) >> 5;
    int lane = threadIdx.x & 31;
    if (node >= N) return;
    int hf = lane >> 4;
    int l16 = lane & 15;
    const uint2* Y2 = (const uint2*)Yh;

    float acc[4];
#pragma unroll
    for (int k = 0; k < 4; k++) acc[k] = 0.f;
    if (hf == 0)
        unpack_add4(Y2[(size_t)node * 16 + l16], acc);

    int end = rowptr[node + 1];
    int j = rowptr[node] + hf;
    for (; j + 6 < end; j += 8) {
        int s0 = __ldg(&col[j]);
        int s1 = __ldg(&col[j + 2]);
        int s2 = __ldg(&col[j + 4]);
        int s3 = __ldg(&col[j + 6]);
        uint2 a = Y2[(size_t)s0 * 16 + l16];
        uint2 b = Y2[(size_t)s1 * 16 + l16];
        uint2 c = Y2[(size_t)s2 * 16 + l16];
        uint2 d = Y2[(size_t)s3 * 16 + l16];
        unpack_add4(a, acc);
        unpack_add4(b, acc);
        unpack_add4(c, acc);
        unpack_add4(d, acc);
    }
    for (; j + 2 < end; j += 4) {
        int s0 = __ldg(&col[j]);
        int s1 = __ldg(&col[j + 2]);
        uint2 a = Y2[(size_t)s0 * 16 + l16];
        uint2 b = Y2[(size_t)s1 * 16 + l16];
        unpack_add4(a, acc);
        unpack_add4(b, acc);
    }
    for (; j < end; j += 2) {
        int s = __ldg(&col[j]);
        unpack_add4(Y2[(size_t)s * 16 + l16], acc);
    }
#pragma unroll
    for (int k = 0; k < 4; k++)
        acc[k] += __shfl_xor_sync(0xFFFFFFFFu, acc[k], 16);

    float di = dinv[node];
    float4 b = ((const float4*)bias)[l16];
    float v0 = fmaf(di, acc[0], b.x);
    float v1 = fmaf(di, acc[1], b.y);
    float v2 = fmaf(di, acc[2], b.z);
    float v3 = fmaf(di, acc[3], b.w);
    float m = fmaxf(fmaxf(v0, v1), fmaxf(v2, v3));
#pragma unroll
    for (int o = 8; o > 0; o >>= 1)
        m = fmaxf(m, __shfl_xor_sync(0xFFFFFFFFu, m, o));
    float s = expf(v0 - m) + expf(v1 - m) + expf(v2 - m) + expf(v3 - m);
#pragma unroll
    for (int o = 8; o > 0; o >>= 1)
        s += __shfl_xor_sync(0xFFFFFFFFu, s, o);
    float ls = m + logf(s);
    if (hf == 0)
        Out[(size_t)node * 16 + l16] = make_float4(v0 - ls, v1 - ls, v2 - ls, v3 - ls);
}

// ---------------- driver ----------------
extern "C" void kernel_launch(void* const* d_in, const int* in_sizes, int n_in,
                              void* d_out, int out_size) {
    const float* x   = (const float*)d_in[0];
    const int*   ei  = (const int*)d_in[1];
    const float* W1  = (const float*)d_in[2];
    const float* b1  = (const float*)d_in[3];
    const float* W2  = (const float*)d_in[4];
    const float* b2  = (const float*)d_in[5];
    const float* W3  = (const float*)d_in[6];
    const float* b3  = (const float*)d_in[7];
    float* out = (float*)d_out;

    int N = in_sizes[0] / 128;
    int E = in_sizes[1] / 2;
    const int* src = ei;
    const int* dst = ei + E;

    __half *yh, *h;
    float* dinv;
    int *cnt, *excl, *bsum, *rowptr, *cursor, *col;
    cudaGetSymbolAddress((void**)&yh, g_yh);
    cudaGetSymbolAddress((void**)&h, g_h);
    cudaGetSymbolAddress((void**)&dinv, g_dinv);
    cudaGetSymbolAddress((void**)&cnt, g_cnt);
    cudaGetSymbolAddress((void**)&excl, g_excl);
    cudaGetSymbolAddress((void**)&bsum, g_bsum);
    cudaGetSymbolAddress((void**)&rowptr, g_rowptr);
    cudaGetSymbolAddress((void**)&cursor, g_cursor);
    cudaGetSymbolAddress((void**)&col, g_col);

    static cudaStream_t s_side = 0;
    static cudaEvent_t ev_fork = 0, ev_join = 0;
    static bool inited = false;
    if (!inited) {
        inited = true;
        if (cudaStreamCreateWithFlags(&s_side, cudaStreamNonBlocking) != cudaSuccess)
            s_side = 0;
        if (s_side) {
            if (cudaEventCreateWithFlags(&ev_fork, cudaEventDisableTiming) != cudaSuccess ||
                cudaEventCreateWithFlags(&ev_join, cudaEventDisableTiming) != cudaSuccess)
                s_side = 0;
        }
    }
    bool fork = (s_side != 0);
    cudaStream_t sc = fork ? s_side : 0;

    constexpr int SMEM_G1    = 128 * 256 + 128 * 256;    // 64 KB
    constexpr int SMEM_CA128 = 2 * 32768 + 128 * 256;    // 96 KB
    constexpr int SMEM_CA64  = 2 * 32768 + 128 * 128;    // 80 KB
    cudaFuncSetAttribute(gemm_hmma_f32,     cudaFuncAttributeMaxDynamicSharedMemorySize, SMEM_G1);
    cudaFuncSetAttribute(gemm_hmma_ca<128>, cudaFuncAttributeMaxDynamicSharedMemorySize, SMEM_CA128);
    cudaFuncSetAttribute(gemm_hmma_ca<64>,  cudaFuncAttributeMaxDynamicSharedMemorySize, SMEM_CA64);

    int nb_nodes = (N + 255) / 256;
    int nb_edges = (E + 255) / 256;
    int nb_scan  = (N + 1023) / 1024;
    int tiles = (N + 127) / 128;
    int gemm_blocks = tiles < 296 ? tiles : 296;
    int agg_blocks  = ((size_t)N * 32 + 255) / 256;

    // ---- fork FROM the capture-origin stream, then prep || gemm1 ----
    if (fork) {
        cudaEventRecord(ev_fork, 0);
        cudaStreamWaitEvent(s_side, ev_fork, 0);
    }
    zero_cnt<<<nb_nodes, 256, 0, sc>>>(cnt, N);
    count_deg<<<nb_edges, 256, 0, sc>>>(dst, cnt, E, N);
    scan_block_dinv<<<nb_scan, 1024, 0, sc>>>(cnt, excl, bsum, dinv, N);
    gemm_hmma_f32<<<gemm_blocks, 256, SMEM_G1>>>(x, W1, yh, N);   // default stream
    scan_partials<<<1, 128, 0, sc>>>(bsum, nb_scan);
    scan_finish<<<(N + 256) / 256, 256, 0, sc>>>(excl, bsum, rowptr, cursor, N, E);
    fill_csr<<<nb_edges, 256, 0, sc>>>(src, dst, cursor, col, E, N);
    if (fork) {
        cudaEventRecord(ev_join, s_side);
        cudaStreamWaitEvent(0, ev_join, 0);
    }

    // ---- layer 1 aggregation ----
    agg_relu128_l1<<<agg_blocks, 256>>>(rowptr, col, yh, dinv, b1, h, N);
    // ---- layer 2 ----
    gemm_hmma_ca<128><<<gemm_blocks, 256, SMEM_CA128>>>(h, W2, dinv, yh, N);
    agg_relu128<<<agg_blocks, 256>>>(rowptr, col, yh, dinv, b2, h, N);
    // ---- layer 3 ----
    gemm_hmma_ca<64><<<gemm_blocks, 256, SMEM_CA64>>>(h, W3, dinv, yh, N);
    agg_lsm64<<<agg_blocks, 256>>>(rowptr, col, yh, dinv, b3, (float4*)out, N);
}